// round 11
// baseline (speedup 1.0000x reference)
#include <cuda_runtime.h>
#include <cuda_bf16.h>
#include <math.h>
#include <stdint.h>

#define S_LEN 2048
#define HID   1024
#define NH    8
#define DK    128
#define DV    128
#define KCONV 4
#define SCALE 0.08838834764831845f   // 128^-0.5
#define EPS   1e-5f

// ---------------------------------------------------------------------------
// Static device scratch
// ---------------------------------------------------------------------------
__device__ float g_qb[S_LEN * HID];
__device__ float g_kb[S_LEN * HID];
__device__ float g_vb[S_LEN * HID];
__device__ float g_qc[S_LEN * HID];
__device__ float g_kc[S_LEN * HID];
__device__ float g_vc[S_LEN * HID];
__device__ float g_gb[S_LEN * HID];
__device__ float g_ob[S_LEN * HID];
__device__ float g_o2[S_LEN * HID];
__device__ float g_alpha[S_LEN * NH];
__device__ float g_beta [S_LEN * NH];

// ---------------------------------------------------------------------------
// SGEMM: C[M,N] = A[M,K] * B[N,K]^T. 128x128 tile, 8x8 microtile, double-buffer.
// ---------------------------------------------------------------------------
__global__ __launch_bounds__(256, 2) void sgemm_tn4(const float* __restrict__ A,
                                                    const float* __restrict__ B0,
                                                    const float* __restrict__ B1,
                                                    const float* __restrict__ B2,
                                                    const float* __restrict__ B3,
                                                    float* __restrict__ C0,
                                                    float* __restrict__ C1,
                                                    float* __restrict__ C2,
                                                    float* __restrict__ C3,
                                                    int M, int N, int K) {
    const int z = blockIdx.z;
    const float* B = (z == 0) ? B0 : (z == 1) ? B1 : (z == 2) ? B2 : B3;
    float*       C = (z == 0) ? C0 : (z == 1) ? C1 : (z == 2) ? C2 : C3;

    __shared__ float As[2][8][128];
    __shared__ float Bs[2][8][128];

    const int tid = threadIdx.x;
    const int bm = blockIdx.y * 128;
    const int bn = blockIdx.x * 128;

    const int lr = tid >> 1;
    const int lc = (tid & 1) * 4;
    const int tx = tid & 15;
    const int ty = tid >> 4;

    float acc[8][8];
#pragma unroll
    for (int i = 0; i < 8; i++)
#pragma unroll
        for (int j = 0; j < 8; j++) acc[i][j] = 0.f;

    float4 av = *reinterpret_cast<const float4*>(&A[(size_t)(bm + lr) * K + lc]);
    float4 bv = *reinterpret_cast<const float4*>(&B[(size_t)(bn + lr) * K + lc]);
    As[0][lc + 0][lr] = av.x; As[0][lc + 1][lr] = av.y;
    As[0][lc + 2][lr] = av.z; As[0][lc + 3][lr] = av.w;
    Bs[0][lc + 0][lr] = bv.x; Bs[0][lc + 1][lr] = bv.y;
    Bs[0][lc + 2][lr] = bv.z; Bs[0][lc + 3][lr] = bv.w;
    __syncthreads();

    for (int kt = 0; kt < K; kt += 8) {
        const int cur = (kt >> 3) & 1;
        const int nxt = cur ^ 1;
        float4 an, bn4;
        const bool has_next = (kt + 8) < K;
        if (has_next) {
            an  = *reinterpret_cast<const float4*>(&A[(size_t)(bm + lr) * K + kt + 8 + lc]);
            bn4 = *reinterpret_cast<const float4*>(&B[(size_t)(bn + lr) * K + kt + 8 + lc]);
        }
#pragma unroll
        for (int kk = 0; kk < 8; kk++) {
            float4 a0 = *reinterpret_cast<const float4*>(&As[cur][kk][ty * 8]);
            float4 a1 = *reinterpret_cast<const float4*>(&As[cur][kk][ty * 8 + 4]);
            float4 b0 = *reinterpret_cast<const float4*>(&Bs[cur][kk][tx * 8]);
            float4 b1 = *reinterpret_cast<const float4*>(&Bs[cur][kk][tx * 8 + 4]);
            float ar[8] = {a0.x, a0.y, a0.z, a0.w, a1.x, a1.y, a1.z, a1.w};
            float br[8] = {b0.x, b0.y, b0.z, b0.w, b1.x, b1.y, b1.z, b1.w};
#pragma unroll
            for (int i = 0; i < 8; i++)
#pragma unroll
                for (int j = 0; j < 8; j++) acc[i][j] = fmaf(ar[i], br[j], acc[i][j]);
        }
        if (has_next) {
            As[nxt][lc + 0][lr] = an.x;  As[nxt][lc + 1][lr] = an.y;
            As[nxt][lc + 2][lr] = an.z;  As[nxt][lc + 3][lr] = an.w;
            Bs[nxt][lc + 0][lr] = bn4.x; Bs[nxt][lc + 1][lr] = bn4.y;
            Bs[nxt][lc + 2][lr] = bn4.z; Bs[nxt][lc + 3][lr] = bn4.w;
            __syncthreads();
        }
    }

#pragma unroll
    for (int i = 0; i < 8; i++) {
        const size_t row = (size_t)(bm + ty * 8 + i) * N + bn + tx * 8;
        *reinterpret_cast<float4*>(&C[row])     = make_float4(acc[i][0], acc[i][1], acc[i][2], acc[i][3]);
        *reinterpret_cast<float4*>(&C[row + 4]) = make_float4(acc[i][4], acc[i][5], acc[i][6], acc[i][7]);
    }
}

// ---------------------------------------------------------------------------
// alpha/beta projections
// ---------------------------------------------------------------------------
__global__ __launch_bounds__(256) void ab_kernel(const float* __restrict__ x,
                                                 const float* __restrict__ Wa,
                                                 const float* __restrict__ ba,
                                                 const float* __restrict__ Wb,
                                                 const float* __restrict__ bb,
                                                 float* __restrict__ alpha,
                                                 float* __restrict__ beta) {
    const int t = blockIdx.x;
    const int w = threadIdx.x >> 5;
    const int lane = threadIdx.x & 31;
    const float* xr = x + (size_t)t * HID;
    const float* war = Wa + (size_t)w * HID;
    const float* wbr = Wb + (size_t)w * HID;
    float sa = 0.f, sb = 0.f;
    for (int i = lane; i < HID; i += 32) {
        float xv = xr[i];
        sa = fmaf(xv, war[i], sa);
        sb = fmaf(xv, wbr[i], sb);
    }
#pragma unroll
    for (int off = 16; off > 0; off >>= 1) {
        sa += __shfl_down_sync(0xffffffffu, sa, off);
        sb += __shfl_down_sync(0xffffffffu, sb, off);
    }
    if (lane == 0) {
        alpha[t * NH + w] = 1.f / (1.f + expf(-(sa + ba[w])));
        beta [t * NH + w] = 1.f / (1.f + expf(-(sb + bb[w])));
    }
}

// ---------------------------------------------------------------------------
// Fused depthwise causal conv (K=4) + bias + SiLU for q/k/v.
// ---------------------------------------------------------------------------
__global__ __launch_bounds__(256) void conv_silu3(const float* __restrict__ inq,
                                                  const float* __restrict__ ink,
                                                  const float* __restrict__ inv,
                                                  const float* __restrict__ wq,
                                                  const float* __restrict__ bq,
                                                  const float* __restrict__ wk,
                                                  const float* __restrict__ bk,
                                                  const float* __restrict__ wv,
                                                  const float* __restrict__ bv,
                                                  float* __restrict__ outq,
                                                  float* __restrict__ outk,
                                                  float* __restrict__ outv) {
    const int z = blockIdx.y;
    const float* in  = (z == 0) ? inq : (z == 1) ? ink : inv;
    const float* w   = (z == 0) ? wq  : (z == 1) ? wk  : wv;
    const float* b   = (z == 0) ? bq  : (z == 1) ? bk  : bv;
    float*       out = (z == 0) ? outq: (z == 1) ? outk: outv;
    const float scale = (z == 1) ? SCALE : 1.0f;

    const int idx = blockIdx.x * 256 + threadIdx.x;
    const int t = idx >> 10;
    const int c = idx & 1023;
    float acc = b[c];
#pragma unroll
    for (int j = 0; j < KCONV; j++) {
        const int tt = t + j - (KCONV - 1);
        if (tt >= 0) acc = fmaf(in[((size_t)tt << 10) + c], w[c * KCONV + j], acc);
    }
    const float sil = acc / (1.f + expf(-acc));
    out[idx] = sil * scale;
}

// ---------------------------------------------------------------------------
// Gated DeltaNet recurrence v6 — warp-autonomous cp.async rings.
//
// 128 blocks (8 heads x 16 row-groups of 8 rows), 128 threads (4 warps).
// Each warp handles 2 rows (16 lanes/row, 8 state floats/lane) and owns a
// PRIVATE 8-stage smem ring for k/q/v/alpha/beta -> no __syncthreads; the
// only per-step sync is __syncwarp (cp.async visibility within the warp).
// Lookahead: dot_{t+1} = a*P + nb*R, P = s_{t-1}.k_{t+1}, R = k_t.k_{t+1}.
// ---------------------------------------------------------------------------
#define NST 8

#define CPA16(dst, src) asm volatile("cp.async.ca.shared.global [%0], [%1], 16;\n" :: "r"(dst), "l"(src))
#define CPA8(dst, src)  asm volatile("cp.async.ca.shared.global [%0], [%1], 8;\n"  :: "r"(dst), "l"(src))
#define CPA4(dst, src)  asm volatile("cp.async.ca.shared.global [%0], [%1], 4;\n"  :: "r"(dst), "l"(src))
#define CPCOMMIT()      asm volatile("cp.async.commit_group;\n" ::: "memory")
#define CPWAIT(n)       asm volatile("cp.async.wait_group %0;\n" :: "n"(n) : "memory")

__global__ __launch_bounds__(128) void recurrence6(const float* __restrict__ q,
                                                   const float* __restrict__ k,
                                                   const float* __restrict__ v,
                                                   const float* __restrict__ alpha,
                                                   const float* __restrict__ beta,
                                                   float* __restrict__ o) {
    const int h  = blockIdx.x >> 4;            // head 0..7
    const int rg = blockIdx.x & 15;            // row group (8 rows)
    const int tid = threadIdx.x;
    const int wid  = tid >> 5;                 // 0..3
    const int lane = tid & 31;
    const int rsel = lane >> 4;                // 0/1: row within warp
    const int row  = rg * 8 + wid * 2 + rsel;  // 0..127
    const int l16  = lane & 15;                // 8-float segment index
    const int hoff = h * DK;

    // per-warp private rings
    __shared__ float sk[4][NST][128];
    __shared__ float sq[4][NST][128];
    __shared__ float sv[4][NST][2];
    __shared__ float sab[4][NST][2];

    // ---- per-lane cp.async roles (all within this warp) ----
    const char* gk = (const char*)(k + hoff + lane * 4);
    const char* gq = (const char*)(q + hoff + lane * 4);
    const unsigned int sdk = (unsigned int)__cvta_generic_to_shared(&sk[wid][0][lane * 4]);
    const unsigned int sdq = (unsigned int)__cvta_generic_to_shared(&sq[wid][0][lane * 4]);
    const char* gv = (const char*)(v + hoff + rg * 8 + wid * 2);      // 2 rows, 8B
    const unsigned int sdv = (unsigned int)__cvta_generic_to_shared(&sv[wid][0][0]);
    const char* ga = (const char*)(alpha + h);
    const char* gb2 = (const char*)(beta + h);
    const unsigned int sda = (unsigned int)__cvta_generic_to_shared(&sab[wid][0][0]);
    const unsigned int sdb = (unsigned int)__cvta_generic_to_shared(&sab[wid][0][1]);

#define ISSUE_STAGE(SLOT_, TG_) {                                             \
    const int tc_ = ((TG_) < S_LEN) ? (TG_) : (S_LEN - 1);                    \
    const size_t go_ = (size_t)tc_ * (HID * 4);                               \
    CPA16(sdk + (SLOT_) * 512, gk + go_);                                     \
    CPA16(sdq + (SLOT_) * 512, gq + go_);                                     \
    if (lane == 0)      { CPA8(sdv + (SLOT_) * 8, gv + go_); }                \
    else if (lane == 1) { CPA4(sda + (SLOT_) * 8, ga + (size_t)tc_ * (NH * 4)); } \
    else if (lane == 2) { CPA4(sdb + (SLOT_) * 8, gb2 + (size_t)tc_ * (NH * 4)); } \
    CPCOMMIT();                                                               \
}

    // prologue: stages 0..NST-2 in flight (7 groups)
#pragma unroll
    for (int i = 0; i < NST - 1; i++) ISSUE_STAGE(i, i);

    float s[8];
#pragma unroll
    for (int j = 0; j < 8; j++) s[j] = 0.f;
    float dot = 0.f;   // s_{-1}.k_0 = 0

    float* op = o + hoff + row;
    const int kbase = l16 * 8;

#define RED16(x_) {                                                           \
    x_ += __shfl_xor_sync(0xffffffffu, x_, 1);                                \
    x_ += __shfl_xor_sync(0xffffffffu, x_, 2);                                \
    x_ += __shfl_xor_sync(0xffffffffu, x_, 4);                                \
    x_ += __shfl_xor_sync(0xffffffffu, x_, 8);                                \
}

    for (int t = 0; t < S_LEN; t++) {
        const int st  = t & (NST - 1);
        const int stn = (t + 1) & (NST - 1);

        CPWAIT(5);          // stages t and t+1 complete (per-thread groups in lockstep)
        __syncwarp();       // cross-lane smem visibility within the warp

        // smem -> regs
        float kk[8], kn[8], qq[8];
        {
            float4 a0 = *reinterpret_cast<const float4*>(&sk[wid][st][kbase]);
            float4 a1 = *reinterpret_cast<const float4*>(&sk[wid][st][kbase + 4]);
            kk[0]=a0.x; kk[1]=a0.y; kk[2]=a0.z; kk[3]=a0.w;
            kk[4]=a1.x; kk[5]=a1.y; kk[6]=a1.z; kk[7]=a1.w;
            float4 b0 = *reinterpret_cast<const float4*>(&sk[wid][stn][kbase]);
            float4 b1 = *reinterpret_cast<const float4*>(&sk[wid][stn][kbase + 4]);
            kn[0]=b0.x; kn[1]=b0.y; kn[2]=b0.z; kn[3]=b0.w;
            kn[4]=b1.x; kn[5]=b1.y; kn[6]=b1.z; kn[7]=b1.w;
            float4 c0 = *reinterpret_cast<const float4*>(&sq[wid][st][kbase]);
            float4 c1 = *reinterpret_cast<const float4*>(&sq[wid][st][kbase + 4]);
            qq[0]=c0.x; qq[1]=c0.y; qq[2]=c0.z; qq[3]=c0.w;
            qq[4]=c1.x; qq[5]=c1.y; qq[6]=c1.z; qq[7]=c1.w;
        }
        const float vv = sv[wid][st][rsel];
        const float aa = sab[wid][st][0];
        const float bb = sab[wid][st][1];

        const float nb = bb * (vv - dot);       // serial scalar chain

        // P = s_{t-1}.k_{t+1}, R = k_t.k_{t+1}  (off-chain)
        float P0=0.f,P1=0.f,P2=0.f,P3=0.f, R0=0.f,R1=0.f,R2=0.f,R3=0.f;
#pragma unroll
        for (int j = 0; j < 8; j += 4) {
            P0 = fmaf(s[j+0], kn[j+0], P0);  R0 = fmaf(kk[j+0], kn[j+0], R0);
            P1 = fmaf(s[j+1], kn[j+1], P1);  R1 = fmaf(kk[j+1], kn[j+1], R1);
            P2 = fmaf(s[j+2], kn[j+2], P2);  R2 = fmaf(kk[j+2], kn[j+2], R2);
            P3 = fmaf(s[j+3], kn[j+3], P3);  R3 = fmaf(kk[j+3], kn[j+3], R3);
        }
        float P = (P0 + P1) + (P2 + P3);
        float R = (R0 + R1) + (R2 + R3);

        // state update + output partials
        float o0=0.f,o1=0.f,o2=0.f,o3=0.f;
#pragma unroll
        for (int j = 0; j < 8; j += 4) {
            float sn0 = fmaf(aa, s[j+0], nb * kk[j+0]);
            float sn1 = fmaf(aa, s[j+1], nb * kk[j+1]);
            float sn2 = fmaf(aa, s[j+2], nb * kk[j+2]);
            float sn3 = fmaf(aa, s[j+3], nb * kk[j+3]);
            s[j+0]=sn0; s[j+1]=sn1; s[j+2]=sn2; s[j+3]=sn3;
            o0 = fmaf(sn0, qq[j+0], o0);  o1 = fmaf(sn1, qq[j+1], o1);
            o2 = fmaf(sn2, qq[j+2], o2);  o3 = fmaf(sn3, qq[j+3], o3);
        }
        float ov = (o0 + o1) + (o2 + o3);

        RED16(P); RED16(R); RED16(ov);
        dot = fmaf(aa, P, nb * R);

        if (l16 == 0) op[(size_t)t * HID] = ov;

        // refill slot t-1 with data for step t+NST-1
        ISSUE_STAGE((t + NST - 1) & (NST - 1), t + NST - 1);
    }
#undef RED16
#undef ISSUE_STAGE
}

// ---------------------------------------------------------------------------
// LayerNorm over DV + sigmoid gate.
// ---------------------------------------------------------------------------
__global__ __launch_bounds__(128) void ln_gate(const float* __restrict__ o,
                                               const float* __restrict__ gb,
                                               const float* __restrict__ ln_g,
                                               const float* __restrict__ ln_b,
                                               float* __restrict__ out) {
    const int row = blockIdx.x;
    const int d = threadIdx.x;
    const size_t idx = (size_t)row * DV + d;
    const float val = o[idx];

    __shared__ float red[4], red2[4];
    float sum = val;
#pragma unroll
    for (int off = 16; off > 0; off >>= 1) sum += __shfl_down_sync(0xffffffffu, sum, off);
    if ((d & 31) == 0) red[d >> 5] = sum;
    __syncthreads();
    const float mu = (red[0] + red[1] + red[2] + red[3]) * (1.f / DV);
    const float diff = val - mu;
    float sq = diff * diff;
#pragma unroll
    for (int off = 16; off > 0; off >>= 1) sq += __shfl_down_sync(0xffffffffu, sq, off);
    if ((d & 31) == 0) red2[d >> 5] = sq;
    __syncthreads();
    const float var = (red2[0] + red2[1] + red2[2] + red2[3]) * (1.f / DV);
    const float y = diff * rsqrtf(var + EPS) * ln_g[d] + ln_b[d];
    const float gate = 1.f / (1.f + expf(-gb[idx]));
    out[idx] = y * gate;
}

// ---------------------------------------------------------------------------
// Launch
// ---------------------------------------------------------------------------
extern "C" void kernel_launch(void* const* d_in, const int* in_sizes, int n_in,
                              void* d_out, int out_size) {
    const float* x       = (const float*)d_in[0];
    const float* Wq      = (const float*)d_in[1];
    const float* Wk      = (const float*)d_in[2];
    const float* Wv      = (const float*)d_in[3];
    const float* cqw     = (const float*)d_in[4];
    const float* cqb     = (const float*)d_in[5];
    const float* ckw     = (const float*)d_in[6];
    const float* ckb     = (const float*)d_in[7];
    const float* cvw     = (const float*)d_in[8];
    const float* cvb     = (const float*)d_in[9];
    const float* Wa      = (const float*)d_in[10];
    const float* ba      = (const float*)d_in[11];
    const float* Wb      = (const float*)d_in[12];
    const float* bb      = (const float*)d_in[13];
    const float* Wg      = (const float*)d_in[14];
    const float* ln_g    = (const float*)d_in[15];
    const float* ln_b    = (const float*)d_in[16];
    const float* Wo      = (const float*)d_in[17];
    float* out = (float*)d_out;

    float *qb, *kb, *vb, *qc, *kc, *vc, *gb, *ob, *o2, *al, *be;
    cudaGetSymbolAddress((void**)&qb, g_qb);
    cudaGetSymbolAddress((void**)&kb, g_kb);
    cudaGetSymbolAddress((void**)&vb, g_vb);
    cudaGetSymbolAddress((void**)&qc, g_qc);
    cudaGetSymbolAddress((void**)&kc, g_kc);
    cudaGetSymbolAddress((void**)&vc, g_vc);
    cudaGetSymbolAddress((void**)&gb, g_gb);
    cudaGetSymbolAddress((void**)&ob, g_ob);
    cudaGetSymbolAddress((void**)&o2, g_o2);
    cudaGetSymbolAddress((void**)&al, g_alpha);
    cudaGetSymbolAddress((void**)&be, g_beta);

    dim3 g4(HID / 128, S_LEN / 128, 4);
    sgemm_tn4<<<g4, 256>>>(x, Wq, Wk, Wv, Wg, qb, kb, vb, gb, S_LEN, HID, HID);

    ab_kernel<<<S_LEN, 256>>>(x, Wa, ba, Wb, bb, al, be);

    dim3 gc(S_LEN * HID / 256, 3);
    conv_silu3<<<gc, 256>>>(qb, kb, vb, cqw, cqb, ckw, ckb, cvw, cvb, qc, kc, vc);

    recurrence6<<<128, 128>>>(qc, kc, vc, al, be, ob);

    ln_gate<<<S_LEN * NH, 128>>>(ob, gb, ln_g, ln_b, o2);

    dim3 g1(HID / 128, S_LEN / 128, 1);
    sgemm_tn4<<<g1, 256>>>(o2, Wo, Wo, Wo, Wo, out, out, out, out, S_LEN, HID, HID);
}

// round 13
// speedup vs baseline: 1.1820x; 1.1820x over previous
#include <cuda_runtime.h>
#include <cuda_bf16.h>
#include <math.h>
#include <stdint.h>

#define S_LEN 2048
#define HID   1024
#define NH    8
#define DK    128
#define DV    128
#define KCONV 4
#define SCALE 0.08838834764831845f   // 128^-0.5
#define EPS   1e-5f

#define CHK    64                     // chunk length
#define NCHUNK 32                     // S_LEN / CHK
#define NCH    (NH * NCHUNK)          // 256 chunk-heads; ch = h*NCHUNK + c

// ---------------------------------------------------------------------------
// Static device scratch
// ---------------------------------------------------------------------------
__device__ float g_qb[S_LEN * HID];
__device__ float g_kb[S_LEN * HID];
__device__ float g_vb[S_LEN * HID];
__device__ float g_qc[S_LEN * HID];
__device__ float g_kc[S_LEN * HID];
__device__ float g_vc[S_LEN * HID];
__device__ float g_gb[S_LEN * HID];
__device__ float g_ob[S_LEN * HID];
__device__ float g_o2[S_LEN * HID];
__device__ float g_alpha[S_LEN * NH];
__device__ float g_beta [S_LEN * NH];
// chunked-recurrence scratch
__device__ float g_Lm1 [NCH * CHK];          // L_{i-1} (cum log-decay, exclusive)
__device__ float g_Lc  [NCH * CHK];          // L_i (inclusive)
__device__ float g_D   [NCH * CHK * CHK];
__device__ float g_Pqk [NCH * CHK * CHK];
__device__ float g_Ti  [NCH * CHK * CHK];
__device__ float g_E   [NCH * CHK * DK];
__device__ float g_W2  [NCH * CHK * DV];
__device__ float g_Kw  [NCH * CHK * DK];
__device__ float g_U   [S_LEN * HID];
__device__ float g_Sc  [NCH * DK * DV];      // chunk-start states (16 MB)

// ---------------------------------------------------------------------------
// SGEMM: C[M,N] = A[M,K] * B[N,K]^T. 128x128 tile, 8x8 microtile, double-buffer.
// ---------------------------------------------------------------------------
__global__ __launch_bounds__(256, 2) void sgemm_tn4(const float* __restrict__ A,
                                                    const float* __restrict__ B0,
                                                    const float* __restrict__ B1,
                                                    const float* __restrict__ B2,
                                                    const float* __restrict__ B3,
                                                    float* __restrict__ C0,
                                                    float* __restrict__ C1,
                                                    float* __restrict__ C2,
                                                    float* __restrict__ C3,
                                                    int M, int N, int K) {
    const int z = blockIdx.z;
    const float* B = (z == 0) ? B0 : (z == 1) ? B1 : (z == 2) ? B2 : B3;
    float*       C = (z == 0) ? C0 : (z == 1) ? C1 : (z == 2) ? C2 : C3;

    __shared__ float As[2][8][128];
    __shared__ float Bs[2][8][128];

    const int tid = threadIdx.x;
    const int bm = blockIdx.y * 128;
    const int bn = blockIdx.x * 128;

    const int lr = tid >> 1;
    const int lc = (tid & 1) * 4;
    const int tx = tid & 15;
    const int ty = tid >> 4;

    float acc[8][8];
#pragma unroll
    for (int i = 0; i < 8; i++)
#pragma unroll
        for (int j = 0; j < 8; j++) acc[i][j] = 0.f;

    float4 av = *reinterpret_cast<const float4*>(&A[(size_t)(bm + lr) * K + lc]);
    float4 bv = *reinterpret_cast<const float4*>(&B[(size_t)(bn + lr) * K + lc]);
    As[0][lc + 0][lr] = av.x; As[0][lc + 1][lr] = av.y;
    As[0][lc + 2][lr] = av.z; As[0][lc + 3][lr] = av.w;
    Bs[0][lc + 0][lr] = bv.x; Bs[0][lc + 1][lr] = bv.y;
    Bs[0][lc + 2][lr] = bv.z; Bs[0][lc + 3][lr] = bv.w;
    __syncthreads();

    for (int kt = 0; kt < K; kt += 8) {
        const int cur = (kt >> 3) & 1;
        const int nxt = cur ^ 1;
        float4 an, bn4;
        const bool has_next = (kt + 8) < K;
        if (has_next) {
            an  = *reinterpret_cast<const float4*>(&A[(size_t)(bm + lr) * K + kt + 8 + lc]);
            bn4 = *reinterpret_cast<const float4*>(&B[(size_t)(bn + lr) * K + kt + 8 + lc]);
        }
#pragma unroll
        for (int kk = 0; kk < 8; kk++) {
            float4 a0 = *reinterpret_cast<const float4*>(&As[cur][kk][ty * 8]);
            float4 a1 = *reinterpret_cast<const float4*>(&As[cur][kk][ty * 8 + 4]);
            float4 b0 = *reinterpret_cast<const float4*>(&Bs[cur][kk][tx * 8]);
            float4 b1 = *reinterpret_cast<const float4*>(&Bs[cur][kk][tx * 8 + 4]);
            float ar[8] = {a0.x, a0.y, a0.z, a0.w, a1.x, a1.y, a1.z, a1.w};
            float br[8] = {b0.x, b0.y, b0.z, b0.w, b1.x, b1.y, b1.z, b1.w};
#pragma unroll
            for (int i = 0; i < 8; i++)
#pragma unroll
                for (int j = 0; j < 8; j++) acc[i][j] = fmaf(ar[i], br[j], acc[i][j]);
        }
        if (has_next) {
            As[nxt][lc + 0][lr] = an.x;  As[nxt][lc + 1][lr] = an.y;
            As[nxt][lc + 2][lr] = an.z;  As[nxt][lc + 3][lr] = an.w;
            Bs[nxt][lc + 0][lr] = bn4.x; Bs[nxt][lc + 1][lr] = bn4.y;
            Bs[nxt][lc + 2][lr] = bn4.z; Bs[nxt][lc + 3][lr] = bn4.w;
            __syncthreads();
        }
    }

#pragma unroll
    for (int i = 0; i < 8; i++) {
        const size_t row = (size_t)(bm + ty * 8 + i) * N + bn + tx * 8;
        *reinterpret_cast<float4*>(&C[row])     = make_float4(acc[i][0], acc[i][1], acc[i][2], acc[i][3]);
        *reinterpret_cast<float4*>(&C[row + 4]) = make_float4(acc[i][4], acc[i][5], acc[i][6], acc[i][7]);
    }
}

// ---------------------------------------------------------------------------
// alpha/beta projections
// ---------------------------------------------------------------------------
__global__ __launch_bounds__(256) void ab_kernel(const float* __restrict__ x,
                                                 const float* __restrict__ Wa,
                                                 const float* __restrict__ ba,
                                                 const float* __restrict__ Wb,
                                                 const float* __restrict__ bb,
                                                 float* __restrict__ alpha,
                                                 float* __restrict__ beta) {
    const int t = blockIdx.x;
    const int w = threadIdx.x >> 5;
    const int lane = threadIdx.x & 31;
    const float* xr = x + (size_t)t * HID;
    const float* war = Wa + (size_t)w * HID;
    const float* wbr = Wb + (size_t)w * HID;
    float sa = 0.f, sb = 0.f;
    for (int i = lane; i < HID; i += 32) {
        float xv = xr[i];
        sa = fmaf(xv, war[i], sa);
        sb = fmaf(xv, wbr[i], sb);
    }
#pragma unroll
    for (int off = 16; off > 0; off >>= 1) {
        sa += __shfl_down_sync(0xffffffffu, sa, off);
        sb += __shfl_down_sync(0xffffffffu, sb, off);
    }
    if (lane == 0) {
        alpha[t * NH + w] = 1.f / (1.f + expf(-(sa + ba[w])));
        beta [t * NH + w] = 1.f / (1.f + expf(-(sb + bb[w])));
    }
}

// ---------------------------------------------------------------------------
// Fused depthwise causal conv (K=4) + bias + SiLU for q/k/v.
// ---------------------------------------------------------------------------
__global__ __launch_bounds__(256) void conv_silu3(const float* __restrict__ inq,
                                                  const float* __restrict__ ink,
                                                  const float* __restrict__ inv,
                                                  const float* __restrict__ wq,
                                                  const float* __restrict__ bq,
                                                  const float* __restrict__ wk,
                                                  const float* __restrict__ bk,
                                                  const float* __restrict__ wv,
                                                  const float* __restrict__ bv,
                                                  float* __restrict__ outq,
                                                  float* __restrict__ outk,
                                                  float* __restrict__ outv) {
    const int z = blockIdx.y;
    const float* in  = (z == 0) ? inq : (z == 1) ? ink : inv;
    const float* w   = (z == 0) ? wq  : (z == 1) ? wk  : wv;
    const float* b   = (z == 0) ? bq  : (z == 1) ? bk  : bv;
    float*       out = (z == 0) ? outq: (z == 1) ? outk: outv;
    const float scale = (z == 1) ? SCALE : 1.0f;

    const int idx = blockIdx.x * 256 + threadIdx.x;
    const int t = idx >> 10;
    const int c = idx & 1023;
    float acc = b[c];
#pragma unroll
    for (int j = 0; j < KCONV; j++) {
        const int tt = t + j - (KCONV - 1);
        if (tt >= 0) acc = fmaf(in[((size_t)tt << 10) + c], w[c * KCONV + j], acc);
    }
    const float sil = acc / (1.f + expf(-acc));
    out[idx] = sil * scale;
}

// ===========================================================================
// Chunked DeltaNet (WY / UT transform). Per head h, chunk c (C=64):
//  L_i = sum_{l<=i} log a_l ; gamma_i = exp(L_{i-1})
//  (I+D) U = diag(b)V - diag(b*gamma) K S'_c,  D_ij = b_i exp(L_{i-1}-L_j)(k_j.k_i), j<i
//  S'_{c+1} = exp(L_{C-1}) S'_c + Kw^T U,  Kw_j = exp(L_{C-1}-L_j) k_j
//  o_i = exp(L_i)(q_i . S'_c) + sum_{j<=i} exp(L_i-L_j)(q_i.k_j) u_j
// ===========================================================================

// A1: per chunk-head log-decay prefix
__global__ __launch_bounds__(64) void decay_scan() {
    const int ch = blockIdx.x;                 // ch = h*NCHUNK + c
    const int h = ch >> 5, c = ch & 31;
    const int i = threadIdx.x;
    __shared__ float la[CHK];
    la[i] = logf(g_alpha[(c * CHK + i) * NH + h]);
    __syncthreads();
    if (i == 0) {
        float run = 0.f;
        for (int j = 0; j < CHK; j++) {
            g_Lm1[ch * CHK + j] = run;
            run += la[j];
            g_Lc[ch * CHK + j] = run;
        }
    }
}

// A2: D = b_i exp(Lm1_i - L_j) (k_j.k_i) for j<i;  Pqk = exp(L_i - L_j)(q_i.k_j) for j<=i
__global__ __launch_bounds__(256) void chunk_mqk() {
    const int ch = blockIdx.x;
    const int h = ch >> 5, c = ch & 31;
    __shared__ float Ks[CHK][129];
    __shared__ float sLm1[CHK], sLc[CHK], sb[CHK];
    const int tid = threadIdx.x;
    for (int idx = tid; idx < CHK * DK; idx += 256) {
        int i = idx >> 7, d = idx & 127;
        Ks[i][d] = g_kc[(size_t)(c * CHK + i) * HID + h * DK + d];
    }
    if (tid < CHK) {
        sLm1[tid] = g_Lm1[ch * CHK + tid];
        sLc[tid]  = g_Lc [ch * CHK + tid];
        sb[tid]   = g_beta[(c * CHK + tid) * NH + h];
    }
    __syncthreads();
    for (int idx = tid; idx < CHK * CHK; idx += 256) {
        int i = idx >> 6, j = idx & 63;
        float val = 0.f;
        if (j < i) {
            float dot = 0.f;
#pragma unroll 8
            for (int d = 0; d < DK; d++) dot = fmaf(Ks[i][d], Ks[j][d], dot);
            val = sb[i] * expf(sLm1[i] - sLc[j]) * dot;
        }
        g_D[(size_t)ch * 4096 + idx] = val;
    }
    for (int idx = tid; idx < CHK * CHK; idx += 256) {
        int i = idx >> 6, j = idx & 63;
        float val = 0.f;
        if (j <= i) {
            const float* qrow = g_qc + (size_t)(c * CHK + i) * HID + h * DK;
            float dot = 0.f;
#pragma unroll 8
            for (int d = 0; d < DK; d++) dot = fmaf(__ldg(qrow + d), Ks[j][d], dot);
            val = expf(sLc[i] - sLc[j]) * dot;
        }
        g_Pqk[(size_t)ch * 4096 + idx] = val;
    }
}

// A3: Tinv = (I+D)^{-1} by forward substitution; columns independent per thread.
__global__ __launch_bounds__(64) void chunk_tinv() {
    const int ch = blockIdx.x;
    __shared__ float Ds[CHK][65];
    __shared__ float Ti[CHK][65];
    const int col = threadIdx.x;
    for (int i = 0; i < CHK; i++) Ds[i][col] = g_D[(size_t)ch * 4096 + i * 64 + col];
    __syncthreads();
    for (int i = 0; i < CHK; i++) {
        float acc = (i == col) ? 1.f : 0.f;
        for (int j = 0; j < i; j++) acc = fmaf(-Ds[i][j], Ti[j][col], acc);
        Ti[i][col] = acc;   // thread only ever reads its own column -> no sync needed
    }
    for (int i = 0; i < CHK; i++) g_Ti[(size_t)ch * 4096 + i * 64 + col] = Ti[i][col];
}

// A4: E = Tinv diag(b*gamma) K;  W2 = Tinv diag(b) V;  Kw_j = exp(L_{C-1}-L_j) k_j
__global__ __launch_bounds__(256) void chunk_ew() {
    const int ch = blockIdx.x;
    const int h = ch >> 5, c = ch & 31;
    __shared__ float Ti[CHK][CHK];          // 16KB
    __shared__ float sbg[CHK], sbb[CHK], skw[CHK];
    const int tid = threadIdx.x;
    for (int idx = tid; idx < CHK * CHK; idx += 256)
        Ti[idx >> 6][idx & 63] = g_Ti[(size_t)ch * 4096 + idx];
    if (tid < CHK) {
        float b = g_beta[(c * CHK + tid) * NH + h];
        sbb[tid] = b;
        sbg[tid] = b * expf(g_Lm1[ch * CHK + tid]);
        skw[tid] = expf(g_Lc[ch * CHK + 63] - g_Lc[ch * CHK + tid]);
    }
    __syncthreads();
    const int d = tid & 127, half = tid >> 7;   // half: i in [half*32, half*32+32)
    float accE[32], accW[32];
#pragma unroll
    for (int r = 0; r < 32; r++) { accE[r] = 0.f; accW[r] = 0.f; }
    for (int j = 0; j < CHK; j++) {
        const size_t go = (size_t)(c * CHK + j) * HID + h * DK + d;
        const float kv = g_kc[go];
        const float vv = g_vc[go];
        if (half == 0) g_Kw[(size_t)ch * 8192 + j * 128 + d] = skw[j] * kv;
        const float ks = sbg[j] * kv;
        const float vs = sbb[j] * vv;
#pragma unroll
        for (int r = 0; r < 32; r++) {
            const int i = half * 32 + r;
            accE[r] = fmaf(Ti[i][j], ks, accE[r]);
            accW[r] = fmaf(Ti[i][j], vs, accW[r]);
        }
    }
#pragma unroll
    for (int r = 0; r < 32; r++) {
        const int i = half * 32 + r;
        g_E [(size_t)ch * 8192 + i * 128 + d] = accE[r];
        g_W2[(size_t)ch * 8192 + i * 128 + d] = accW[r];
    }
}

// B: sequential over 32 chunks; 128 CTAs = 8 heads x 16 DV-column slices of 8.
__global__ __launch_bounds__(256) void chunk_scan_seq() {
    const int h = blockIdx.x >> 4, slice = blockIdx.x & 15;
    const int c0 = slice * 8;
    __shared__ float EK[CHK][DK];     // 32KB, holds E then Kw
    __shared__ float sp[DK][8];       // state slice S'[d][col]
    __shared__ float Us[CHK][8];
    const int tid = threadIdx.x;
    for (int idx = tid; idx < DK * 8; idx += 256) sp[idx >> 3][idx & 7] = 0.f;
    __syncthreads();

    for (int c = 0; c < NCHUNK; c++) {
        const int ch = h * NCHUNK + c;
        // snapshot chunk-start state
        for (int idx = tid; idx < DK * 8; idx += 256) {
            int d = idx >> 3, cc = idx & 7;
            g_Sc[(size_t)ch * 16384 + d * 128 + c0 + cc] = sp[d][cc];
        }
        // load E
        for (int idx = tid; idx < CHK * DK; idx += 256)
            EK[idx >> 7][idx & 127] = g_E[(size_t)ch * 8192 + idx];
        __syncthreads();
        // U = W2 - E S'
        {
            const int j = tid >> 2, cp = (tid & 3) * 2;
            const size_t wo = (size_t)ch * 8192 + j * 128 + c0 + cp;
            float u0 = g_W2[wo], u1 = g_W2[wo + 1];
#pragma unroll 8
            for (int d = 0; d < DK; d++) {
                const float e = EK[j][d];
                u0 = fmaf(-e, sp[d][cp], u0);
                u1 = fmaf(-e, sp[d][cp + 1], u1);
            }
            Us[j][cp] = u0; Us[j][cp + 1] = u1;
            const size_t go = (size_t)(c * CHK + j) * HID + h * DK + c0 + cp;
            g_U[go] = u0; g_U[go + 1] = u1;
        }
        __syncthreads();
        // load Kw over E
        for (int idx = tid; idx < CHK * DK; idx += 256)
            EK[idx >> 7][idx & 127] = g_Kw[(size_t)ch * 8192 + idx];
        const float lam = expf(g_Lc[ch * CHK + 63]);
        __syncthreads();
        // S' = lam*S' + Kw^T U
        {
            const int d = tid >> 1, cq = (tid & 1) * 4;
            float a0 = lam * sp[d][cq + 0];
            float a1 = lam * sp[d][cq + 1];
            float a2 = lam * sp[d][cq + 2];
            float a3 = lam * sp[d][cq + 3];
#pragma unroll 8
            for (int j = 0; j < CHK; j++) {
                const float kw = EK[j][d];
                a0 = fmaf(kw, Us[j][cq + 0], a0);
                a1 = fmaf(kw, Us[j][cq + 1], a1);
                a2 = fmaf(kw, Us[j][cq + 2], a2);
                a3 = fmaf(kw, Us[j][cq + 3], a3);
            }
            sp[d][cq + 0] = a0; sp[d][cq + 1] = a1;
            sp[d][cq + 2] = a2; sp[d][cq + 3] = a3;
        }
        __syncthreads();
    }
}

// C: O = diag(exp L)(Q S'_c) + Pqk U ;  1024 blocks = 256 chunk-heads x 4 col-quarters
__global__ __launch_bounds__(256) void chunk_out() {
    const int ch = blockIdx.x >> 2, qq = blockIdx.x & 3;
    const int h = ch >> 5, c = ch & 31;
    const int cb = qq * 32;
    __shared__ float Ps[CHK][65];     // 16.25KB
    __shared__ float Uss[CHK][32];    // 8KB
    __shared__ float Scs[DK][32];     // 16KB
    __shared__ float sLi[CHK];
    const int tid = threadIdx.x;
    for (int idx = tid; idx < CHK * CHK; idx += 256)
        Ps[idx >> 6][idx & 63] = g_Pqk[(size_t)ch * 4096 + idx];
    for (int idx = tid; idx < CHK * 32; idx += 256) {
        int j = idx >> 5, cc = idx & 31;
        Uss[j][cc] = g_U[(size_t)(c * CHK + j) * HID + h * DK + cb + cc];
    }
    for (int idx = tid; idx < DK * 32; idx += 256) {
        int d = idx >> 5, cc = idx & 31;
        Scs[d][cc] = g_Sc[(size_t)ch * 16384 + d * 128 + cb + cc];
    }
    if (tid < CHK) sLi[tid] = expf(g_Lc[ch * CHK + tid]);
    __syncthreads();

    const int i = tid >> 2, c8 = (tid & 3) * 8;
    float acc[8];
#pragma unroll
    for (int r = 0; r < 8; r++) acc[r] = 0.f;
    const float* qrow = g_qc + (size_t)(c * CHK + i) * HID + h * DK;
#pragma unroll 4
    for (int d = 0; d < DK; d++) {
        const float qv = __ldg(qrow + d);
#pragma unroll
        for (int r = 0; r < 8; r++) acc[r] = fmaf(qv, Scs[d][c8 + r], acc[r]);
    }
    const float gi = sLi[i];
#pragma unroll
    for (int r = 0; r < 8; r++) acc[r] *= gi;
#pragma unroll 4
    for (int j = 0; j < CHK; j++) {
        const float p = Ps[i][j];
#pragma unroll
        for (int r = 0; r < 8; r++) acc[r] = fmaf(p, Uss[j][c8 + r], acc[r]);
    }
    const size_t go = (size_t)(c * CHK + i) * HID + h * DK + cb + c8;
#pragma unroll
    for (int r = 0; r < 8; r++) g_ob[go + r] = acc[r];
}

// ---------------------------------------------------------------------------
// LayerNorm over DV + sigmoid gate.
// ---------------------------------------------------------------------------
__global__ __launch_bounds__(128) void ln_gate(const float* __restrict__ o,
                                               const float* __restrict__ gb,
                                               const float* __restrict__ ln_g,
                                               const float* __restrict__ ln_b,
                                               float* __restrict__ out) {
    const int row = blockIdx.x;
    const int d = threadIdx.x;
    const size_t idx = (size_t)row * DV + d;
    const float val = o[idx];

    __shared__ float red[4], red2[4];
    float sum = val;
#pragma unroll
    for (int off = 16; off > 0; off >>= 1) sum += __shfl_down_sync(0xffffffffu, sum, off);
    if ((d & 31) == 0) red[d >> 5] = sum;
    __syncthreads();
    const float mu = (red[0] + red[1] + red[2] + red[3]) * (1.f / DV);
    const float diff = val - mu;
    float sq = diff * diff;
#pragma unroll
    for (int off = 16; off > 0; off >>= 1) sq += __shfl_down_sync(0xffffffffu, sq, off);
    if ((d & 31) == 0) red2[d >> 5] = sq;
    __syncthreads();
    const float var = (red2[0] + red2[1] + red2[2] + red2[3]) * (1.f / DV);
    const float y = diff * rsqrtf(var + EPS) * ln_g[d] + ln_b[d];
    const float gate = 1.f / (1.f + expf(-gb[idx]));
    out[idx] = y * gate;
}

// ---------------------------------------------------------------------------
// Launch
// ---------------------------------------------------------------------------
extern "C" void kernel_launch(void* const* d_in, const int* in_sizes, int n_in,
                              void* d_out, int out_size) {
    const float* x       = (const float*)d_in[0];
    const float* Wq      = (const float*)d_in[1];
    const float* Wk      = (const float*)d_in[2];
    const float* Wv      = (const float*)d_in[3];
    const float* cqw     = (const float*)d_in[4];
    const float* cqb     = (const float*)d_in[5];
    const float* ckw     = (const float*)d_in[6];
    const float* ckb     = (const float*)d_in[7];
    const float* cvw     = (const float*)d_in[8];
    const float* cvb     = (const float*)d_in[9];
    const float* Wa      = (const float*)d_in[10];
    const float* ba      = (const float*)d_in[11];
    const float* Wb      = (const float*)d_in[12];
    const float* bb      = (const float*)d_in[13];
    const float* Wg      = (const float*)d_in[14];
    const float* ln_g    = (const float*)d_in[15];
    const float* ln_b    = (const float*)d_in[16];
    const float* Wo      = (const float*)d_in[17];
    float* out = (float*)d_out;

    float *qb, *kb, *vb, *qc, *kc, *vc, *gb, *ob, *o2, *al, *be;
    cudaGetSymbolAddress((void**)&qb, g_qb);
    cudaGetSymbolAddress((void**)&kb, g_kb);
    cudaGetSymbolAddress((void**)&vb, g_vb);
    cudaGetSymbolAddress((void**)&qc, g_qc);
    cudaGetSymbolAddress((void**)&kc, g_kc);
    cudaGetSymbolAddress((void**)&vc, g_vc);
    cudaGetSymbolAddress((void**)&gb, g_gb);
    cudaGetSymbolAddress((void**)&ob, g_ob);
    cudaGetSymbolAddress((void**)&o2, g_o2);
    cudaGetSymbolAddress((void**)&al, g_alpha);
    cudaGetSymbolAddress((void**)&be, g_beta);

    dim3 g4(HID / 128, S_LEN / 128, 4);
    sgemm_tn4<<<g4, 256>>>(x, Wq, Wk, Wv, Wg, qb, kb, vb, gb, S_LEN, HID, HID);

    ab_kernel<<<S_LEN, 256>>>(x, Wa, ba, Wb, bb, al, be);

    dim3 gc(S_LEN * HID / 256, 3);
    conv_silu3<<<gc, 256>>>(qb, kb, vb, cqw, cqb, ckw, ckb, cvw, cvb, qc, kc, vc);

    // chunked recurrence pipeline
    decay_scan   <<<NCH, 64>>>();
    chunk_mqk    <<<NCH, 256>>>();
    chunk_tinv   <<<NCH, 64>>>();
    chunk_ew     <<<NCH, 256>>>();
    chunk_scan_seq<<<128, 256>>>();
    chunk_out    <<<NCH * 4, 256>>>();

    ln_gate<<<S_LEN * NH, 128>>>(ob, gb, ln_g, ln_b, o2);

    dim3 g1(HID / 128, S_LEN / 128, 1);
    sgemm_tn4<<<g1, 256>>>(o2, Wo, Wo, Wo, Wo, out, out, out, out, S_LEN, HID, HID);
}

// round 16
// speedup vs baseline: 1.8245x; 1.5436x over previous
#include <cuda_runtime.h>
#include <cuda_bf16.h>
#include <math.h>
#include <stdint.h>

#define S_LEN 2048
#define HID   1024
#define NH    8
#define DK    128
#define DV    128
#define KCONV 4
#define SCALE 0.08838834764831845f   // 128^-0.5
#define EPS   1e-5f

#define CHK    64
#define NCHUNK 32
#define NCH    (NH * NCHUNK)

// ---------------------------------------------------------------------------
// Static device scratch
// ---------------------------------------------------------------------------
__device__ float g_qb[S_LEN * HID];
__device__ float g_kb[S_LEN * HID];
__device__ float g_vb[S_LEN * HID];
__device__ float g_qc[S_LEN * HID];
__device__ float g_kc[S_LEN * HID];
__device__ float g_vc[S_LEN * HID];
__device__ float g_gb[S_LEN * HID];
__device__ float g_ob[S_LEN * HID];
__device__ float g_o2[S_LEN * HID];
__device__ float g_alpha[S_LEN * NH];
__device__ float g_beta [S_LEN * NH];
// chunked-recurrence scratch
__device__ float g_Lm1 [NCH * CHK];
__device__ float g_Lc  [NCH * CHK];
__device__ float g_D   [NCH * CHK * CHK];
__device__ float g_Pqk [NCH * CHK * CHK];
__device__ float g_Ti  [NCH * CHK * CHK];
__device__ float g_E   [NCH * CHK * DK];
__device__ float g_W2  [NCH * CHK * DV];
__device__ float g_Kw  [NCH * CHK * DK];
__device__ float g_U   [S_LEN * HID];
__device__ float g_Sc  [NCH * DK * DV];

// ===========================================================================
// bf16x3 HMMA GEMM (mma.sync m16n8k16 — base sm_100 compatible):
// C[M,N] = A[M,K] * B[N,K]^T with A,B split hi+lo bf16;
// C = Ah*Bh + Ah*Bl + Al*Bh accumulated in fp32 registers.
// Block tile 128(M) x 64(N), K-chunks of 32; 8 warps (4 m-groups x 2 n-groups),
// each warp owns a 32x32 sub-tile = 2x4 mma tiles of 16x8.
// ===========================================================================
#define STR 40   // bf16 elements per smem row (stride); conflict-free for frags

__device__ __forceinline__ void mma_bf16(float& c0, float& c1, float& c2, float& c3,
                                         unsigned a0, unsigned a1, unsigned a2, unsigned a3,
                                         unsigned b0, unsigned b1) {
    asm volatile("mma.sync.aligned.m16n8k16.row.col.f32.bf16.bf16.f32 "
                 "{%0,%1,%2,%3}, {%4,%5,%6,%7}, {%8,%9}, {%0,%1,%2,%3};"
                 : "+f"(c0), "+f"(c1), "+f"(c2), "+f"(c3)
                 : "r"(a0), "r"(a1), "r"(a2), "r"(a3), "r"(b0), "r"(b1));
}

__global__ __launch_bounds__(256) void mm_bf16x3(const float* __restrict__ A,
                                                 const float* __restrict__ B0,
                                                 const float* __restrict__ B1,
                                                 const float* __restrict__ B2,
                                                 const float* __restrict__ B3,
                                                 float* __restrict__ C0,
                                                 float* __restrict__ C1,
                                                 float* __restrict__ C2,
                                                 float* __restrict__ C3) {
    const int z = blockIdx.z;
    const float* B = (z == 0) ? B0 : (z == 1) ? B1 : (z == 2) ? B2 : B3;
    float*       C = (z == 0) ? C0 : (z == 1) ? C1 : (z == 2) ? C2 : C3;
    const int bm = blockIdx.y * 128;
    const int bn = blockIdx.x * 64;
    const int tid = threadIdx.x, wid = tid >> 5, lane = tid & 31;
    const int warp_m = wid & 3, warp_n = wid >> 2;

    __shared__ __nv_bfloat16 Ah[128 * STR], Al[128 * STR];
    __shared__ __nv_bfloat16 Bh[64 * STR],  Bl[64 * STR];

    float acc[2][4][4];
#pragma unroll
    for (int mt = 0; mt < 2; mt++)
#pragma unroll
        for (int nt = 0; nt < 4; nt++)
#pragma unroll
            for (int r = 0; r < 4; r++) acc[mt][nt][r] = 0.f;

#define SPLIT2(x0_, x1_, H_, L_, eoff_) {                                      \
    __nv_bfloat16 h0_ = __float2bfloat16(x0_), h1_ = __float2bfloat16(x1_);    \
    __nv_bfloat16 l0_ = __float2bfloat16((x0_) - __bfloat162float(h0_));       \
    __nv_bfloat16 l1_ = __float2bfloat16((x1_) - __bfloat162float(h1_));       \
    *(unsigned*)&H_[eoff_] = ((unsigned)__bfloat16_as_ushort(h1_) << 16)       \
                             | __bfloat16_as_ushort(h0_);                      \
    *(unsigned*)&L_[eoff_] = ((unsigned)__bfloat16_as_ushort(l1_) << 16)       \
                             | __bfloat16_as_ushort(l0_);                      \
}

    for (int kt = 0; kt < HID / 32; kt++) {
        // stage A: 128x32 fp32 -> bf16 hi/lo. 1024 float4, 4 per thread.
#pragma unroll
        for (int it = 0; it < 4; it++) {
            const int idx = tid + it * 256;
            const int r = idx >> 3, c4 = (idx & 7) * 4;
            float4 a4 = __ldg(reinterpret_cast<const float4*>(
                A + (size_t)(bm + r) * HID + kt * 32 + c4));
            const int eo = r * STR + c4;
            SPLIT2(a4.x, a4.y, Ah, Al, eo);
            SPLIT2(a4.z, a4.w, Ah, Al, eo + 2);
        }
        // stage B: 64x32. 512 float4, 2 per thread.
#pragma unroll
        for (int it = 0; it < 2; it++) {
            const int idx = tid + it * 256;
            const int r = idx >> 3, c4 = (idx & 7) * 4;
            float4 b4 = __ldg(reinterpret_cast<const float4*>(
                B + (size_t)(bn + r) * HID + kt * 32 + c4));
            const int eo = r * STR + c4;
            SPLIT2(b4.x, b4.y, Bh, Bl, eo);
            SPLIT2(b4.z, b4.w, Bh, Bl, eo + 2);
        }
        __syncthreads();

#pragma unroll
        for (int kk = 0; kk < 32; kk += 16) {
            const int acol = (lane & 3) * 2 + kk;
            unsigned ah[2][4], al[2][4], bh[4][2], bl[4][2];
#pragma unroll
            for (int mt = 0; mt < 2; mt++) {
                const int ar = warp_m * 32 + mt * 16 + (lane >> 2);
                ah[mt][0] = *(unsigned*)&Ah[ar * STR + acol];
                ah[mt][1] = *(unsigned*)&Ah[(ar + 8) * STR + acol];
                ah[mt][2] = *(unsigned*)&Ah[ar * STR + acol + 8];
                ah[mt][3] = *(unsigned*)&Ah[(ar + 8) * STR + acol + 8];
                al[mt][0] = *(unsigned*)&Al[ar * STR + acol];
                al[mt][1] = *(unsigned*)&Al[(ar + 8) * STR + acol];
                al[mt][2] = *(unsigned*)&Al[ar * STR + acol + 8];
                al[mt][3] = *(unsigned*)&Al[(ar + 8) * STR + acol + 8];
            }
#pragma unroll
            for (int nt = 0; nt < 4; nt++) {
                const int br = warp_n * 32 + nt * 8 + (lane >> 2);
                bh[nt][0] = *(unsigned*)&Bh[br * STR + acol];
                bh[nt][1] = *(unsigned*)&Bh[br * STR + acol + 8];
                bl[nt][0] = *(unsigned*)&Bl[br * STR + acol];
                bl[nt][1] = *(unsigned*)&Bl[br * STR + acol + 8];
            }
#pragma unroll
            for (int mt = 0; mt < 2; mt++)
#pragma unroll
                for (int nt = 0; nt < 4; nt++) {
                    float* c = acc[mt][nt];
                    mma_bf16(c[0], c[1], c[2], c[3],
                             ah[mt][0], ah[mt][1], ah[mt][2], ah[mt][3],
                             bh[nt][0], bh[nt][1]);
                    mma_bf16(c[0], c[1], c[2], c[3],
                             ah[mt][0], ah[mt][1], ah[mt][2], ah[mt][3],
                             bl[nt][0], bl[nt][1]);
                    mma_bf16(c[0], c[1], c[2], c[3],
                             al[mt][0], al[mt][1], al[mt][2], al[mt][3],
                             bh[nt][0], bh[nt][1]);
                }
        }
        __syncthreads();
    }

    // epilogue
#pragma unroll
    for (int mt = 0; mt < 2; mt++) {
        const int row0 = bm + warp_m * 32 + mt * 16 + (lane >> 2);
#pragma unroll
        for (int nt = 0; nt < 4; nt++) {
            const int col = bn + warp_n * 32 + nt * 8 + (lane & 3) * 2;
            *reinterpret_cast<float2*>(C + (size_t)row0 * HID + col) =
                make_float2(acc[mt][nt][0], acc[mt][nt][1]);
            *reinterpret_cast<float2*>(C + (size_t)(row0 + 8) * HID + col) =
                make_float2(acc[mt][nt][2], acc[mt][nt][3]);
        }
    }
#undef SPLIT2
}

// ---------------------------------------------------------------------------
// alpha/beta projections
// ---------------------------------------------------------------------------
__global__ __launch_bounds__(256) void ab_kernel(const float* __restrict__ x,
                                                 const float* __restrict__ Wa,
                                                 const float* __restrict__ ba,
                                                 const float* __restrict__ Wb,
                                                 const float* __restrict__ bb,
                                                 float* __restrict__ alpha,
                                                 float* __restrict__ beta) {
    const int t = blockIdx.x;
    const int w = threadIdx.x >> 5;
    const int lane = threadIdx.x & 31;
    const float* xr = x + (size_t)t * HID;
    const float* war = Wa + (size_t)w * HID;
    const float* wbr = Wb + (size_t)w * HID;
    float sa = 0.f, sb = 0.f;
    for (int i = lane; i < HID; i += 32) {
        float xv = xr[i];
        sa = fmaf(xv, war[i], sa);
        sb = fmaf(xv, wbr[i], sb);
    }
#pragma unroll
    for (int off = 16; off > 0; off >>= 1) {
        sa += __shfl_down_sync(0xffffffffu, sa, off);
        sb += __shfl_down_sync(0xffffffffu, sb, off);
    }
    if (lane == 0) {
        alpha[t * NH + w] = 1.f / (1.f + expf(-(sa + ba[w])));
        beta [t * NH + w] = 1.f / (1.f + expf(-(sb + bb[w])));
    }
}

// ---------------------------------------------------------------------------
// Fused depthwise causal conv (K=4) + bias + SiLU for q/k/v.
// ---------------------------------------------------------------------------
__global__ __launch_bounds__(256) void conv_silu3(const float* __restrict__ inq,
                                                  const float* __restrict__ ink,
                                                  const float* __restrict__ inv,
                                                  const float* __restrict__ wq,
                                                  const float* __restrict__ bq,
                                                  const float* __restrict__ wk,
                                                  const float* __restrict__ bk,
                                                  const float* __restrict__ wv,
                                                  const float* __restrict__ bv,
                                                  float* __restrict__ outq,
                                                  float* __restrict__ outk,
                                                  float* __restrict__ outv) {
    const int z = blockIdx.y;
    const float* in  = (z == 0) ? inq : (z == 1) ? ink : inv;
    const float* w   = (z == 0) ? wq  : (z == 1) ? wk  : wv;
    const float* b   = (z == 0) ? bq  : (z == 1) ? bk  : bv;
    float*       out = (z == 0) ? outq: (z == 1) ? outk: outv;
    const float scale = (z == 1) ? SCALE : 1.0f;

    const int idx = blockIdx.x * 256 + threadIdx.x;
    const int t = idx >> 10;
    const int c = idx & 1023;
    float acc = b[c];
#pragma unroll
    for (int j = 0; j < KCONV; j++) {
        const int tt = t + j - (KCONV - 1);
        if (tt >= 0) acc = fmaf(in[((size_t)tt << 10) + c], w[c * KCONV + j], acc);
    }
    const float sil = acc / (1.f + expf(-acc));
    out[idx] = sil * scale;
}

// ===========================================================================
// Chunked DeltaNet (WY / UT transform)
// ===========================================================================
__global__ __launch_bounds__(64) void decay_scan() {
    const int ch = blockIdx.x;
    const int h = ch >> 5, c = ch & 31;
    const int i = threadIdx.x;
    __shared__ float la[CHK];
    la[i] = logf(g_alpha[(c * CHK + i) * NH + h]);
    __syncthreads();
    if (i == 0) {
        float run = 0.f;
        for (int j = 0; j < CHK; j++) {
            g_Lm1[ch * CHK + j] = run;
            run += la[j];
            g_Lc[ch * CHK + j] = run;
        }
    }
}

__global__ __launch_bounds__(256) void chunk_mqk() {
    const int ch = blockIdx.x;
    const int h = ch >> 5, c = ch & 31;
    __shared__ float Ks[CHK][129];
    __shared__ float sLm1[CHK], sLc[CHK], sb[CHK];
    const int tid = threadIdx.x;
    for (int idx = tid; idx < CHK * DK; idx += 256) {
        int i = idx >> 7, d = idx & 127;
        Ks[i][d] = g_kc[(size_t)(c * CHK + i) * HID + h * DK + d];
    }
    if (tid < CHK) {
        sLm1[tid] = g_Lm1[ch * CHK + tid];
        sLc[tid]  = g_Lc [ch * CHK + tid];
        sb[tid]   = g_beta[(c * CHK + tid) * NH + h];
    }
    __syncthreads();
    for (int idx = tid; idx < CHK * CHK; idx += 256) {
        int i = idx >> 6, j = idx & 63;
        float val = 0.f;
        if (j < i) {
            float dot = 0.f;
#pragma unroll 8
            for (int d = 0; d < DK; d++) dot = fmaf(Ks[i][d], Ks[j][d], dot);
            val = sb[i] * expf(sLm1[i] - sLc[j]) * dot;
        }
        g_D[(size_t)ch * 4096 + idx] = val;
    }
    for (int idx = tid; idx < CHK * CHK; idx += 256) {
        int i = idx >> 6, j = idx & 63;
        float val = 0.f;
        if (j <= i) {
            const float* qrow = g_qc + (size_t)(c * CHK + i) * HID + h * DK;
            float dot = 0.f;
#pragma unroll 8
            for (int d = 0; d < DK; d++) dot = fmaf(__ldg(qrow + d), Ks[j][d], dot);
            val = expf(sLc[i] - sLc[j]) * dot;
        }
        g_Pqk[(size_t)ch * 4096 + idx] = val;
    }
}

__global__ __launch_bounds__(64) void chunk_tinv() {
    const int ch = blockIdx.x;
    __shared__ float Ds[CHK][65];
    __shared__ float Ti[CHK][65];
    const int col = threadIdx.x;
    for (int i = 0; i < CHK; i++) Ds[i][col] = g_D[(size_t)ch * 4096 + i * 64 + col];
    __syncthreads();
    for (int i = 0; i < CHK; i++) {
        float acc = (i == col) ? 1.f : 0.f;
        for (int j = 0; j < i; j++) acc = fmaf(-Ds[i][j], Ti[j][col], acc);
        Ti[i][col] = acc;
    }
    for (int i = 0; i < CHK; i++) g_Ti[(size_t)ch * 4096 + i * 64 + col] = Ti[i][col];
}

__global__ __launch_bounds__(256) void chunk_ew() {
    const int ch = blockIdx.x;
    const int h = ch >> 5, c = ch & 31;
    __shared__ float Ti[CHK][CHK];
    __shared__ float sbg[CHK], sbb[CHK], skw[CHK];
    const int tid = threadIdx.x;
    for (int idx = tid; idx < CHK * CHK; idx += 256)
        Ti[idx >> 6][idx & 63] = g_Ti[(size_t)ch * 4096 + idx];
    if (tid < CHK) {
        float b = g_beta[(c * CHK + tid) * NH + h];
        sbb[tid] = b;
        sbg[tid] = b * expf(g_Lm1[ch * CHK + tid]);
        skw[tid] = expf(g_Lc[ch * CHK + 63] - g_Lc[ch * CHK + tid]);
    }
    __syncthreads();
    const int d = tid & 127, half = tid >> 7;
    float accE[32], accW[32];
#pragma unroll
    for (int r = 0; r < 32; r++) { accE[r] = 0.f; accW[r] = 0.f; }
    for (int j = 0; j < CHK; j++) {
        const size_t go = (size_t)(c * CHK + j) * HID + h * DK + d;
        const float kv = g_kc[go];
        const float vv = g_vc[go];
        if (half == 0) g_Kw[(size_t)ch * 8192 + j * 128 + d] = skw[j] * kv;
        const float ks = sbg[j] * kv;
        const float vs = sbb[j] * vv;
#pragma unroll
        for (int r = 0; r < 32; r++) {
            const int i = half * 32 + r;
            accE[r] = fmaf(Ti[i][j], ks, accE[r]);
            accW[r] = fmaf(Ti[i][j], vs, accW[r]);
        }
    }
#pragma unroll
    for (int r = 0; r < 32; r++) {
        const int i = half * 32 + r;
        g_E [(size_t)ch * 8192 + i * 128 + d] = accE[r];
        g_W2[(size_t)ch * 8192 + i * 128 + d] = accW[r];
    }
}

__global__ __launch_bounds__(256) void chunk_scan_seq() {
    const int h = blockIdx.x >> 4, slice = blockIdx.x & 15;
    const int c0 = slice * 8;
    __shared__ float EK[CHK][DK];
    __shared__ float sp[DK][8];
    __shared__ float Us[CHK][8];
    const int tid = threadIdx.x;
    for (int idx = tid; idx < DK * 8; idx += 256) sp[idx >> 3][idx & 7] = 0.f;
    __syncthreads();

    for (int c = 0; c < NCHUNK; c++) {
        const int ch = h * NCHUNK + c;
        for (int idx = tid; idx < DK * 8; idx += 256) {
            int d = idx >> 3, cc = idx & 7;
            g_Sc[(size_t)ch * 16384 + d * 128 + c0 + cc] = sp[d][cc];
        }
        for (int idx = tid; idx < CHK * DK / 4; idx += 256)
            reinterpret_cast<float4*>(&EK[0][0])[idx] =
                __ldg(reinterpret_cast<const float4*>(g_E + (size_t)ch * 8192) + idx);
        __syncthreads();
        {
            const int j = tid >> 2, cp = (tid & 3) * 2;
            const size_t wo = (size_t)ch * 8192 + j * 128 + c0 + cp;
            float2 w2 = __ldg(reinterpret_cast<const float2*>(g_W2 + wo));
            float u0 = w2.x, u1 = w2.y;
#pragma unroll 8
            for (int d = 0; d < DK; d++) {
                const float e = EK[j][d];
                u0 = fmaf(-e, sp[d][cp], u0);
                u1 = fmaf(-e, sp[d][cp + 1], u1);
            }
            Us[j][cp] = u0; Us[j][cp + 1] = u1;
            const size_t go = (size_t)(c * CHK + j) * HID + h * DK + c0 + cp;
            g_U[go] = u0; g_U[go + 1] = u1;
        }
        __syncthreads();
        for (int idx = tid; idx < CHK * DK / 4; idx += 256)
            reinterpret_cast<float4*>(&EK[0][0])[idx] =
                __ldg(reinterpret_cast<const float4*>(g_Kw + (size_t)ch * 8192) + idx);
        const float lam = expf(g_Lc[ch * CHK + 63]);
        __syncthreads();
        {
            const int d = tid >> 1, cq = (tid & 1) * 4;
            float a0 = lam * sp[d][cq + 0];
            float a1 = lam * sp[d][cq + 1];
            float a2 = lam * sp[d][cq + 2];
            float a3 = lam * sp[d][cq + 3];
#pragma unroll 8
            for (int j = 0; j < CHK; j++) {
                const float kw = EK[j][d];
                a0 = fmaf(kw, Us[j][cq + 0], a0);
                a1 = fmaf(kw, Us[j][cq + 1], a1);
                a2 = fmaf(kw, Us[j][cq + 2], a2);
                a3 = fmaf(kw, Us[j][cq + 3], a3);
            }
            sp[d][cq + 0] = a0; sp[d][cq + 1] = a1;
            sp[d][cq + 2] = a2; sp[d][cq + 3] = a3;
        }
        __syncthreads();
    }
}

__global__ __launch_bounds__(256) void chunk_out() {
    const int ch = blockIdx.x >> 2, qq = blockIdx.x & 3;
    const int h = ch >> 5, c = ch & 31;
    const int cb = qq * 32;
    __shared__ float Ps[CHK][65];
    __shared__ float Uss[CHK][32];
    __shared__ float Scs[DK][32];
    __shared__ float sLi[CHK];
    const int tid = threadIdx.x;
    for (int idx = tid; idx < CHK * CHK; idx += 256)
        Ps[idx >> 6][idx & 63] = g_Pqk[(size_t)ch * 4096 + idx];
    for (int idx = tid; idx < CHK * 32; idx += 256) {
        int j = idx >> 5, cc = idx & 31;
        Uss[j][cc] = g_U[(size_t)(c * CHK + j) * HID + h * DK + cb + cc];
    }
    for (int idx = tid; idx < DK * 32; idx += 256) {
        int d = idx >> 5, cc = idx & 31;
        Scs[d][cc] = g_Sc[(size_t)ch * 16384 + d * 128 + cb + cc];
    }
    if (tid < CHK) sLi[tid] = expf(g_Lc[ch * CHK + tid]);
    __syncthreads();

    const int i = tid >> 2, c8 = (tid & 3) * 8;
    float acc[8];
#pragma unroll
    for (int r = 0; r < 8; r++) acc[r] = 0.f;
    const float* qrow = g_qc + (size_t)(c * CHK + i) * HID + h * DK;
#pragma unroll 4
    for (int d = 0; d < DK; d++) {
        const float qv = __ldg(qrow + d);
#pragma unroll
        for (int r = 0; r < 8; r++) acc[r] = fmaf(qv, Scs[d][c8 + r], acc[r]);
    }
    const float gi = sLi[i];
#pragma unroll
    for (int r = 0; r < 8; r++) acc[r] *= gi;
#pragma unroll 4
    for (int j = 0; j < CHK; j++) {
        const float p = Ps[i][j];
#pragma unroll
        for (int r = 0; r < 8; r++) acc[r] = fmaf(p, Uss[j][c8 + r], acc[r]);
    }
    const size_t go = (size_t)(c * CHK + i) * HID + h * DK + cb + c8;
#pragma unroll
    for (int r = 0; r < 8; r++) g_ob[go + r] = acc[r];
}

// ---------------------------------------------------------------------------
// LayerNorm over DV + sigmoid gate.
// ---------------------------------------------------------------------------
__global__ __launch_bounds__(128) void ln_gate(const float* __restrict__ o,
                                               const float* __restrict__ gb,
                                               const float* __restrict__ ln_g,
                                               const float* __restrict__ ln_b,
                                               float* __restrict__ out) {
    const int row = blockIdx.x;
    const int d = threadIdx.x;
    const size_t idx = (size_t)row * DV + d;
    const float val = o[idx];

    __shared__ float red[4], red2[4];
    float sum = val;
#pragma unroll
    for (int off = 16; off > 0; off >>= 1) sum += __shfl_down_sync(0xffffffffu, sum, off);
    if ((d & 31) == 0) red[d >> 5] = sum;
    __syncthreads();
    const float mu = (red[0] + red[1] + red[2] + red[3]) * (1.f / DV);
    const float diff = val - mu;
    float sq = diff * diff;
#pragma unroll
    for (int off = 16; off > 0; off >>= 1) sq += __shfl_down_sync(0xffffffffu, sq, off);
    if ((d & 31) == 0) red2[d >> 5] = sq;
    __syncthreads();
    const float var = (red2[0] + red2[1] + red2[2] + red2[3]) * (1.f / DV);
    const float y = diff * rsqrtf(var + EPS) * ln_g[d] + ln_b[d];
    const float gate = 1.f / (1.f + expf(-gb[idx]));
    out[idx] = y * gate;
}

// ---------------------------------------------------------------------------
// Launch
// ---------------------------------------------------------------------------
extern "C" void kernel_launch(void* const* d_in, const int* in_sizes, int n_in,
                              void* d_out, int out_size) {
    const float* x       = (const float*)d_in[0];
    const float* Wq      = (const float*)d_in[1];
    const float* Wk      = (const float*)d_in[2];
    const float* Wv      = (const float*)d_in[3];
    const float* cqw     = (const float*)d_in[4];
    const float* cqb     = (const float*)d_in[5];
    const float* ckw     = (const float*)d_in[6];
    const float* ckb     = (const float*)d_in[7];
    const float* cvw     = (const float*)d_in[8];
    const float* cvb     = (const float*)d_in[9];
    const float* Wa      = (const float*)d_in[10];
    const float* ba      = (const float*)d_in[11];
    const float* Wb      = (const float*)d_in[12];
    const float* bb      = (const float*)d_in[13];
    const float* Wg      = (const float*)d_in[14];
    const float* ln_g    = (const float*)d_in[15];
    const float* ln_b    = (const float*)d_in[16];
    const float* Wo      = (const float*)d_in[17];
    float* out = (float*)d_out;

    float *qb, *kb, *vb, *qc, *kc, *vc, *gb, *ob, *o2, *al, *be;
    cudaGetSymbolAddress((void**)&qb, g_qb);
    cudaGetSymbolAddress((void**)&kb, g_kb);
    cudaGetSymbolAddress((void**)&vb, g_vb);
    cudaGetSymbolAddress((void**)&qc, g_qc);
    cudaGetSymbolAddress((void**)&kc, g_kc);
    cudaGetSymbolAddress((void**)&vc, g_vc);
    cudaGetSymbolAddress((void**)&gb, g_gb);
    cudaGetSymbolAddress((void**)&ob, g_ob);
    cudaGetSymbolAddress((void**)&o2, g_o2);
    cudaGetSymbolAddress((void**)&al, g_alpha);
    cudaGetSymbolAddress((void**)&be, g_beta);

    // bf16x3 HMMA projections: grid (N/64, M/128, 4)
    dim3 gp(HID / 64, S_LEN / 128, 4);
    mm_bf16x3<<<gp, 256>>>(x, Wq, Wk, Wv, Wg, qb, kb, vb, gb);

    ab_kernel<<<S_LEN, 256>>>(x, Wa, ba, Wb, bb, al, be);

    dim3 gc(S_LEN * HID / 256, 3);
    conv_silu3<<<gc, 256>>>(qb, kb, vb, cqw, cqb, ckw, ckb, cvw, cvb, qc, kc, vc);

    decay_scan   <<<NCH, 64>>>();
    chunk_mqk    <<<NCH, 256>>>();
    chunk_tinv   <<<NCH, 64>>>();
    chunk_ew     <<<NCH, 256>>>();
    chunk_scan_seq<<<128, 256>>>();
    chunk_out    <<<NCH * 4, 256>>>();

    ln_gate<<<S_LEN * NH, 128>>>(ob, gb, ln_g, ln_b, o2);

    dim3 go(HID / 64, S_LEN / 128, 1);
    mm_bf16x3<<<go, 256>>>(o2, Wo, Wo, Wo, Wo, out, out, out, out);
}

// round 17
// speedup vs baseline: 1.9347x; 1.0604x over previous
#include <cuda_runtime.h>
#include <cuda_bf16.h>
#include <math.h>
#include <stdint.h>

#define S_LEN 2048
#define HID   1024
#define NH    8
#define DK    128
#define DV    128
#define KCONV 4
#define SCALE 0.08838834764831845f   // 128^-0.5
#define EPS   1e-5f

#define CHK    64
#define NCHUNK 32
#define NCH    (NH * NCHUNK)

// ---------------------------------------------------------------------------
// Static device scratch
// ---------------------------------------------------------------------------
__device__ float g_qb[S_LEN * HID];
__device__ float g_kb[S_LEN * HID];
__device__ float g_vb[S_LEN * HID];
__device__ float g_qc[S_LEN * HID];
__device__ float g_kc[S_LEN * HID];
__device__ float g_vc[S_LEN * HID];
__device__ float g_gb[S_LEN * HID];
__device__ float g_ob[S_LEN * HID];
__device__ float g_o2[S_LEN * HID];
__device__ float g_alpha[S_LEN * NH];
__device__ float g_beta [S_LEN * NH];
// chunked-recurrence scratch
__device__ float g_Lm1 [NCH * CHK];
__device__ float g_Lc  [NCH * CHK];
__device__ float g_D   [NCH * CHK * CHK];
__device__ float g_Pqk [NCH * CHK * CHK];
__device__ float g_Ti  [NCH * CHK * CHK];
__device__ float g_E   [NCH * CHK * DK];
__device__ float g_W2  [NCH * CHK * DV];
__device__ float g_Kw  [NCH * CHK * DK];
__device__ float g_U   [S_LEN * HID];
__device__ float g_Sc  [NCH * DK * DV];
// pre-split bf16 operands
__device__ __nv_bfloat16 g_xh[S_LEN * HID], g_xl[S_LEN * HID];
__device__ __nv_bfloat16 g_wh[5 * HID * HID], g_wl[5 * HID * HID];

// ---------------------------------------------------------------------------
// fp32 -> bf16 hi/lo split (elementwise, 4 per thread)
// ---------------------------------------------------------------------------
__global__ __launch_bounds__(256) void split_bf16(const float* __restrict__ s,
                                                  __nv_bfloat16* __restrict__ h,
                                                  __nv_bfloat16* __restrict__ l) {
    const int i = (blockIdx.x * 256 + threadIdx.x) * 4;
    float4 v = __ldg(reinterpret_cast<const float4*>(s + i));
    __nv_bfloat16 h0 = __float2bfloat16(v.x), h1 = __float2bfloat16(v.y);
    __nv_bfloat16 h2 = __float2bfloat16(v.z), h3 = __float2bfloat16(v.w);
    __nv_bfloat16 l0 = __float2bfloat16(v.x - __bfloat162float(h0));
    __nv_bfloat16 l1 = __float2bfloat16(v.y - __bfloat162float(h1));
    __nv_bfloat16 l2 = __float2bfloat16(v.z - __bfloat162float(h2));
    __nv_bfloat16 l3 = __float2bfloat16(v.w - __bfloat162float(h3));
    uint2 ph, pl;
    ph.x = ((unsigned)__bfloat16_as_ushort(h1) << 16) | __bfloat16_as_ushort(h0);
    ph.y = ((unsigned)__bfloat16_as_ushort(h3) << 16) | __bfloat16_as_ushort(h2);
    pl.x = ((unsigned)__bfloat16_as_ushort(l1) << 16) | __bfloat16_as_ushort(l0);
    pl.y = ((unsigned)__bfloat16_as_ushort(l3) << 16) | __bfloat16_as_ushort(l2);
    *reinterpret_cast<uint2*>(h + i) = ph;
    *reinterpret_cast<uint2*>(l + i) = pl;
}

// ===========================================================================
// bf16x3 HMMA GEMM on PRE-SPLIT operands.
// C[M,N] = A[M,K] * B[N,K]^T; C = Ah*Bh + Ah*Bl + Al*Bh (fp32 accum).
// Block tile 128x64, K-chunks of 32; 8 warps, 32x32 per warp (2x4 m16n8 tiles).
// ===========================================================================
#define STR 40

__device__ __forceinline__ void mma_bf16(float& c0, float& c1, float& c2, float& c3,
                                         unsigned a0, unsigned a1, unsigned a2, unsigned a3,
                                         unsigned b0, unsigned b1) {
    asm volatile("mma.sync.aligned.m16n8k16.row.col.f32.bf16.bf16.f32 "
                 "{%0,%1,%2,%3}, {%4,%5,%6,%7}, {%8,%9}, {%0,%1,%2,%3};"
                 : "+f"(c0), "+f"(c1), "+f"(c2), "+f"(c3)
                 : "r"(a0), "r"(a1), "r"(a2), "r"(a3), "r"(b0), "r"(b1));
}

__global__ __launch_bounds__(256) void mm_pre(const __nv_bfloat16* __restrict__ Ahg,
                                              const __nv_bfloat16* __restrict__ Alg,
                                              const __nv_bfloat16* __restrict__ Whg,
                                              const __nv_bfloat16* __restrict__ Wlg,
                                              float* __restrict__ C0,
                                              float* __restrict__ C1,
                                              float* __restrict__ C2,
                                              float* __restrict__ C3) {
    const int z = blockIdx.z;
    float* C = (z == 0) ? C0 : (z == 1) ? C1 : (z == 2) ? C2 : C3;
    const __nv_bfloat16* Bhg = Whg + (size_t)z * HID * HID;
    const __nv_bfloat16* Blg = Wlg + (size_t)z * HID * HID;
    const int bm = blockIdx.y * 128;
    const int bn = blockIdx.x * 64;
    const int tid = threadIdx.x, wid = tid >> 5, lane = tid & 31;
    const int warp_m = wid & 3, warp_n = wid >> 2;

    __shared__ __nv_bfloat16 Ah[128 * STR], Al[128 * STR];
    __shared__ __nv_bfloat16 Bh[64 * STR],  Bl[64 * STR];

    float acc[2][4][4];
#pragma unroll
    for (int mt = 0; mt < 2; mt++)
#pragma unroll
        for (int nt = 0; nt < 4; nt++)
#pragma unroll
            for (int r = 0; r < 4; r++) acc[mt][nt][r] = 0.f;

    for (int kt = 0; kt < HID / 32; kt++) {
        // A: 128 rows x 32 cols = 512 uint4 (8 bf16 each); 2 per thread.
#pragma unroll
        for (int it = 0; it < 2; it++) {
            const int i = tid + it * 256;
            const int r = i >> 2, part = i & 3;
            const size_t go = (size_t)(bm + r) * HID + kt * 32 + part * 8;
            uint4 vh = __ldg(reinterpret_cast<const uint4*>(Ahg + go));
            uint4 vl = __ldg(reinterpret_cast<const uint4*>(Alg + go));
            *reinterpret_cast<uint4*>(&Ah[r * STR + part * 8]) = vh;
            *reinterpret_cast<uint4*>(&Al[r * STR + part * 8]) = vl;
        }
        // B: 64 rows x 32 cols = 256 uint4; 1 per thread.
        {
            const int r = tid >> 2, part = tid & 3;
            const size_t go = (size_t)(bn + r) * HID + kt * 32 + part * 8;
            uint4 vh = __ldg(reinterpret_cast<const uint4*>(Bhg + go));
            uint4 vl = __ldg(reinterpret_cast<const uint4*>(Blg + go));
            *reinterpret_cast<uint4*>(&Bh[r * STR + part * 8]) = vh;
            *reinterpret_cast<uint4*>(&Bl[r * STR + part * 8]) = vl;
        }
        __syncthreads();

#pragma unroll
        for (int kk = 0; kk < 32; kk += 16) {
            const int acol = (lane & 3) * 2 + kk;
            unsigned ah[2][4], al[2][4], bh[4][2], bl[4][2];
#pragma unroll
            for (int mt = 0; mt < 2; mt++) {
                const int ar = warp_m * 32 + mt * 16 + (lane >> 2);
                ah[mt][0] = *(unsigned*)&Ah[ar * STR + acol];
                ah[mt][1] = *(unsigned*)&Ah[(ar + 8) * STR + acol];
                ah[mt][2] = *(unsigned*)&Ah[ar * STR + acol + 8];
                ah[mt][3] = *(unsigned*)&Ah[(ar + 8) * STR + acol + 8];
                al[mt][0] = *(unsigned*)&Al[ar * STR + acol];
                al[mt][1] = *(unsigned*)&Al[(ar + 8) * STR + acol];
                al[mt][2] = *(unsigned*)&Al[ar * STR + acol + 8];
                al[mt][3] = *(unsigned*)&Al[(ar + 8) * STR + acol + 8];
            }
#pragma unroll
            for (int nt = 0; nt < 4; nt++) {
                const int br = warp_n * 32 + nt * 8 + (lane >> 2);
                bh[nt][0] = *(unsigned*)&Bh[br * STR + acol];
                bh[nt][1] = *(unsigned*)&Bh[br * STR + acol + 8];
                bl[nt][0] = *(unsigned*)&Bl[br * STR + acol];
                bl[nt][1] = *(unsigned*)&Bl[br * STR + acol + 8];
            }
#pragma unroll
            for (int mt = 0; mt < 2; mt++)
#pragma unroll
                for (int nt = 0; nt < 4; nt++) {
                    float* c = acc[mt][nt];
                    mma_bf16(c[0], c[1], c[2], c[3],
                             ah[mt][0], ah[mt][1], ah[mt][2], ah[mt][3],
                             bh[nt][0], bh[nt][1]);
                    mma_bf16(c[0], c[1], c[2], c[3],
                             ah[mt][0], ah[mt][1], ah[mt][2], ah[mt][3],
                             bl[nt][0], bl[nt][1]);
                    mma_bf16(c[0], c[1], c[2], c[3],
                             al[mt][0], al[mt][1], al[mt][2], al[mt][3],
                             bh[nt][0], bh[nt][1]);
                }
        }
        __syncthreads();
    }

#pragma unroll
    for (int mt = 0; mt < 2; mt++) {
        const int row0 = bm + warp_m * 32 + mt * 16 + (lane >> 2);
#pragma unroll
        for (int nt = 0; nt < 4; nt++) {
            const int col = bn + warp_n * 32 + nt * 8 + (lane & 3) * 2;
            *reinterpret_cast<float2*>(C + (size_t)row0 * HID + col) =
                make_float2(acc[mt][nt][0], acc[mt][nt][1]);
            *reinterpret_cast<float2*>(C + (size_t)(row0 + 8) * HID + col) =
                make_float2(acc[mt][nt][2], acc[mt][nt][3]);
        }
    }
}

// ---------------------------------------------------------------------------
// alpha/beta projections
// ---------------------------------------------------------------------------
__global__ __launch_bounds__(256) void ab_kernel(const float* __restrict__ x,
                                                 const float* __restrict__ Wa,
                                                 const float* __restrict__ ba,
                                                 const float* __restrict__ Wb,
                                                 const float* __restrict__ bb,
                                                 float* __restrict__ alpha,
                                                 float* __restrict__ beta) {
    const int t = blockIdx.x;
    const int w = threadIdx.x >> 5;
    const int lane = threadIdx.x & 31;
    const float* xr = x + (size_t)t * HID;
    const float* war = Wa + (size_t)w * HID;
    const float* wbr = Wb + (size_t)w * HID;
    float sa = 0.f, sb = 0.f;
    for (int i = lane; i < HID; i += 32) {
        float xv = xr[i];
        sa = fmaf(xv, war[i], sa);
        sb = fmaf(xv, wbr[i], sb);
    }
#pragma unroll
    for (int off = 16; off > 0; off >>= 1) {
        sa += __shfl_down_sync(0xffffffffu, sa, off);
        sb += __shfl_down_sync(0xffffffffu, sb, off);
    }
    if (lane == 0) {
        alpha[t * NH + w] = 1.f / (1.f + expf(-(sa + ba[w])));
        beta [t * NH + w] = 1.f / (1.f + expf(-(sb + bb[w])));
    }
}

// ---------------------------------------------------------------------------
// Fused depthwise causal conv (K=4) + bias + SiLU for q/k/v.
// ---------------------------------------------------------------------------
__global__ __launch_bounds__(256) void conv_silu3(const float* __restrict__ inq,
                                                  const float* __restrict__ ink,
                                                  const float* __restrict__ inv,
                                                  const float* __restrict__ wq,
                                                  const float* __restrict__ bq,
                                                  const float* __restrict__ wk,
                                                  const float* __restrict__ bk,
                                                  const float* __restrict__ wv,
                                                  const float* __restrict__ bv,
                                                  float* __restrict__ outq,
                                                  float* __restrict__ outk,
                                                  float* __restrict__ outv) {
    const int z = blockIdx.y;
    const float* in  = (z == 0) ? inq : (z == 1) ? ink : inv;
    const float* w   = (z == 0) ? wq  : (z == 1) ? wk  : wv;
    const float* b   = (z == 0) ? bq  : (z == 1) ? bk  : bv;
    float*       out = (z == 0) ? outq: (z == 1) ? outk: outv;
    const float scale = (z == 1) ? SCALE : 1.0f;

    const int idx = blockIdx.x * 256 + threadIdx.x;
    const int t = idx >> 10;
    const int c = idx & 1023;
    float acc = b[c];
#pragma unroll
    for (int j = 0; j < KCONV; j++) {
        const int tt = t + j - (KCONV - 1);
        if (tt >= 0) acc = fmaf(in[((size_t)tt << 10) + c], w[c * KCONV + j], acc);
    }
    const float sil = acc / (1.f + expf(-acc));
    out[idx] = sil * scale;
}

// ===========================================================================
// Chunked DeltaNet (WY / UT transform)
// ===========================================================================
__global__ __launch_bounds__(64) void decay_scan() {
    const int ch = blockIdx.x;
    const int h = ch >> 5, c = ch & 31;
    const int i = threadIdx.x;
    __shared__ float la[CHK];
    la[i] = logf(g_alpha[(c * CHK + i) * NH + h]);
    __syncthreads();
    if (i == 0) {
        float run = 0.f;
        for (int j = 0; j < CHK; j++) {
            g_Lm1[ch * CHK + j] = run;
            run += la[j];
            g_Lc[ch * CHK + j] = run;
        }
    }
}

// A2 (register-tiled): D and Pqk via 4x4 microtiles on a 16x16 thread grid.
__global__ __launch_bounds__(256) void chunk_mqk() {
    const int ch = blockIdx.x;
    const int h = ch >> 5, c = ch & 31;
    __shared__ float Ks[CHK][129];
    __shared__ float sLm1[CHK], sLc[CHK], sb[CHK];
    const int tid = threadIdx.x;
    for (int idx = tid; idx < CHK * DK; idx += 256) {
        int i = idx >> 7, d = idx & 127;
        Ks[i][d] = g_kc[(size_t)(c * CHK + i) * HID + h * DK + d];
    }
    if (tid < CHK) {
        sLm1[tid] = g_Lm1[ch * CHK + tid];
        sLc[tid]  = g_Lc [ch * CHK + tid];
        sb[tid]   = g_beta[(c * CHK + tid) * NH + h];
    }
    __syncthreads();

    const int ty = tid >> 4, tx = tid & 15;
    const int i0 = ty * 4, j0 = tx * 4;
    float aD[4][4], aP[4][4];
#pragma unroll
    for (int r = 0; r < 4; r++)
#pragma unroll
        for (int s = 0; s < 4; s++) { aD[r][s] = 0.f; aP[r][s] = 0.f; }

    const float* qbase = g_qc + (size_t)(c * CHK + i0) * HID + h * DK;
    for (int d = 0; d < DK; d++) {
        float kj[4];
#pragma unroll
        for (int s = 0; s < 4; s++) kj[s] = Ks[j0 + s][d];
#pragma unroll
        for (int r = 0; r < 4; r++) {
            const float ki = Ks[i0 + r][d];
            const float qi = __ldg(qbase + (size_t)r * HID + d);
#pragma unroll
            for (int s = 0; s < 4; s++) {
                aD[r][s] = fmaf(ki, kj[s], aD[r][s]);
                aP[r][s] = fmaf(qi, kj[s], aP[r][s]);
            }
        }
    }
#pragma unroll
    for (int r = 0; r < 4; r++) {
        const int i = i0 + r;
#pragma unroll
        for (int s = 0; s < 4; s++) {
            const int j = j0 + s;
            float dv = 0.f, pv = 0.f;
            if (j < i)  dv = sb[i] * expf(sLm1[i] - sLc[j]) * aD[r][s];
            if (j <= i) pv = expf(sLc[i] - sLc[j]) * aP[r][s];
            g_D  [(size_t)ch * 4096 + i * 64 + j] = dv;
            g_Pqk[(size_t)ch * 4096 + i * 64 + j] = pv;
        }
    }
}

__global__ __launch_bounds__(64) void chunk_tinv() {
    const int ch = blockIdx.x;
    __shared__ float Ds[CHK][65];
    __shared__ float Ti[CHK][65];
    const int col = threadIdx.x;
    for (int i = 0; i < CHK; i++) Ds[i][col] = g_D[(size_t)ch * 4096 + i * 64 + col];
    __syncthreads();
    for (int i = 0; i < CHK; i++) {
        float acc = (i == col) ? 1.f : 0.f;
        for (int j = 0; j < i; j++) acc = fmaf(-Ds[i][j], Ti[j][col], acc);
        Ti[i][col] = acc;
    }
    for (int i = 0; i < CHK; i++) g_Ti[(size_t)ch * 4096 + i * 64 + col] = Ti[i][col];
}

__global__ __launch_bounds__(256) void chunk_ew() {
    const int ch = blockIdx.x;
    const int h = ch >> 5, c = ch & 31;
    __shared__ float Ti[CHK][CHK];
    __shared__ float sbg[CHK], sbb[CHK], skw[CHK];
    const int tid = threadIdx.x;
    for (int idx = tid; idx < CHK * CHK; idx += 256)
        Ti[idx >> 6][idx & 63] = g_Ti[(size_t)ch * 4096 + idx];
    if (tid < CHK) {
        float b = g_beta[(c * CHK + tid) * NH + h];
        sbb[tid] = b;
        sbg[tid] = b * expf(g_Lm1[ch * CHK + tid]);
        skw[tid] = expf(g_Lc[ch * CHK + 63] - g_Lc[ch * CHK + tid]);
    }
    __syncthreads();
    const int d = tid & 127, half = tid >> 7;
    float accE[32], accW[32];
#pragma unroll
    for (int r = 0; r < 32; r++) { accE[r] = 0.f; accW[r] = 0.f; }
    for (int j = 0; j < CHK; j++) {
        const size_t go = (size_t)(c * CHK + j) * HID + h * DK + d;
        const float kv = g_kc[go];
        const float vv = g_vc[go];
        if (half == 0) g_Kw[(size_t)ch * 8192 + j * 128 + d] = skw[j] * kv;
        const float ks = sbg[j] * kv;
        const float vs = sbb[j] * vv;
#pragma unroll
        for (int r = 0; r < 32; r++) {
            const int i = half * 32 + r;
            accE[r] = fmaf(Ti[i][j], ks, accE[r]);
            accW[r] = fmaf(Ti[i][j], vs, accW[r]);
        }
    }
#pragma unroll
    for (int r = 0; r < 32; r++) {
        const int i = half * 32 + r;
        g_E [(size_t)ch * 8192 + i * 128 + d] = accE[r];
        g_W2[(size_t)ch * 8192 + i * 128 + d] = accW[r];
    }
}

__global__ __launch_bounds__(256) void chunk_scan_seq() {
    const int h = blockIdx.x >> 4, slice = blockIdx.x & 15;
    const int c0 = slice * 8;
    __shared__ float EK[CHK][DK];
    __shared__ float sp[DK][8];
    __shared__ float Us[CHK][8];
    const int tid = threadIdx.x;
    for (int idx = tid; idx < DK * 8; idx += 256) sp[idx >> 3][idx & 7] = 0.f;
    __syncthreads();

    for (int c = 0; c < NCHUNK; c++) {
        const int ch = h * NCHUNK + c;
        for (int idx = tid; idx < DK * 8; idx += 256) {
            int d = idx >> 3, cc = idx & 7;
            g_Sc[(size_t)ch * 16384 + d * 128 + c0 + cc] = sp[d][cc];
        }
        for (int idx = tid; idx < CHK * DK / 4; idx += 256)
            reinterpret_cast<float4*>(&EK[0][0])[idx] =
                __ldg(reinterpret_cast<const float4*>(g_E + (size_t)ch * 8192) + idx);
        __syncthreads();
        {
            const int j = tid >> 2, cp = (tid & 3) * 2;
            const size_t wo = (size_t)ch * 8192 + j * 128 + c0 + cp;
            float2 w2 = __ldg(reinterpret_cast<const float2*>(g_W2 + wo));
            float u0 = w2.x, u1 = w2.y;
#pragma unroll 8
            for (int d = 0; d < DK; d++) {
                const float e = EK[j][d];
                u0 = fmaf(-e, sp[d][cp], u0);
                u1 = fmaf(-e, sp[d][cp + 1], u1);
            }
            Us[j][cp] = u0; Us[j][cp + 1] = u1;
            const size_t go = (size_t)(c * CHK + j) * HID + h * DK + c0 + cp;
            g_U[go] = u0; g_U[go + 1] = u1;
        }
        __syncthreads();
        for (int idx = tid; idx < CHK * DK / 4; idx += 256)
            reinterpret_cast<float4*>(&EK[0][0])[idx] =
                __ldg(reinterpret_cast<const float4*>(g_Kw + (size_t)ch * 8192) + idx);
        const float lam = expf(g_Lc[ch * CHK + 63]);
        __syncthreads();
        {
            const int d = tid >> 1, cq = (tid & 1) * 4;
            float a0 = lam * sp[d][cq + 0];
            float a1 = lam * sp[d][cq + 1];
            float a2 = lam * sp[d][cq + 2];
            float a3 = lam * sp[d][cq + 3];
#pragma unroll 8
            for (int j = 0; j < CHK; j++) {
                const float kw = EK[j][d];
                a0 = fmaf(kw, Us[j][cq + 0], a0);
                a1 = fmaf(kw, Us[j][cq + 1], a1);
                a2 = fmaf(kw, Us[j][cq + 2], a2);
                a3 = fmaf(kw, Us[j][cq + 3], a3);
            }
            sp[d][cq + 0] = a0; sp[d][cq + 1] = a1;
            sp[d][cq + 2] = a2; sp[d][cq + 3] = a3;
        }
        __syncthreads();
    }
}

__global__ __launch_bounds__(256) void chunk_out() {
    const int ch = blockIdx.x >> 2, qq = blockIdx.x & 3;
    const int h = ch >> 5, c = ch & 31;
    const int cb = qq * 32;
    __shared__ float Ps[CHK][65];
    __shared__ float Uss[CHK][32];
    __shared__ float Scs[DK][32];
    __shared__ float sLi[CHK];
    const int tid = threadIdx.x;
    for (int idx = tid; idx < CHK * CHK; idx += 256)
        Ps[idx >> 6][idx & 63] = g_Pqk[(size_t)ch * 4096 + idx];
    for (int idx = tid; idx < CHK * 32; idx += 256) {
        int j = idx >> 5, cc = idx & 31;
        Uss[j][cc] = g_U[(size_t)(c * CHK + j) * HID + h * DK + cb + cc];
    }
    for (int idx = tid; idx < DK * 32; idx += 256) {
        int d = idx >> 5, cc = idx & 31;
        Scs[d][cc] = g_Sc[(size_t)ch * 16384 + d * 128 + cb + cc];
    }
    if (tid < CHK) sLi[tid] = expf(g_Lc[ch * CHK + tid]);
    __syncthreads();

    const int i = tid >> 2, c8 = (tid & 3) * 8;
    float acc[8];
#pragma unroll
    for (int r = 0; r < 8; r++) acc[r] = 0.f;
    const float* qrow = g_qc + (size_t)(c * CHK + i) * HID + h * DK;
#pragma unroll 4
    for (int d = 0; d < DK; d++) {
        const float qv = __ldg(qrow + d);
#pragma unroll
        for (int r = 0; r < 8; r++) acc[r] = fmaf(qv, Scs[d][c8 + r], acc[r]);
    }
    const float gi = sLi[i];
#pragma unroll
    for (int r = 0; r < 8; r++) acc[r] *= gi;
#pragma unroll 4
    for (int j = 0; j < CHK; j++) {
        const float p = Ps[i][j];
#pragma unroll
        for (int r = 0; r < 8; r++) acc[r] = fmaf(p, Uss[j][c8 + r], acc[r]);
    }
    const size_t go = (size_t)(c * CHK + i) * HID + h * DK + cb + c8;
#pragma unroll
    for (int r = 0; r < 8; r++) g_ob[go + r] = acc[r];
}

// ---------------------------------------------------------------------------
// LayerNorm over DV + sigmoid gate.
// ---------------------------------------------------------------------------
__global__ __launch_bounds__(128) void ln_gate(const float* __restrict__ o,
                                               const float* __restrict__ gb,
                                               const float* __restrict__ ln_g,
                                               const float* __restrict__ ln_b,
                                               float* __restrict__ out) {
    const int row = blockIdx.x;
    const int d = threadIdx.x;
    const size_t idx = (size_t)row * DV + d;
    const float val = o[idx];

    __shared__ float red[4], red2[4];
    float sum = val;
#pragma unroll
    for (int off = 16; off > 0; off >>= 1) sum += __shfl_down_sync(0xffffffffu, sum, off);
    if ((d & 31) == 0) red[d >> 5] = sum;
    __syncthreads();
    const float mu = (red[0] + red[1] + red[2] + red[3]) * (1.f / DV);
    const float diff = val - mu;
    float sq = diff * diff;
#pragma unroll
    for (int off = 16; off > 0; off >>= 1) sq += __shfl_down_sync(0xffffffffu, sq, off);
    if ((d & 31) == 0) red2[d >> 5] = sq;
    __syncthreads();
    const float var = (red2[0] + red2[1] + red2[2] + red2[3]) * (1.f / DV);
    const float y = diff * rsqrtf(var + EPS) * ln_g[d] + ln_b[d];
    const float gate = 1.f / (1.f + expf(-gb[idx]));
    out[idx] = y * gate;
}

// ---------------------------------------------------------------------------
// Launch
// ---------------------------------------------------------------------------
extern "C" void kernel_launch(void* const* d_in, const int* in_sizes, int n_in,
                              void* d_out, int out_size) {
    const float* x       = (const float*)d_in[0];
    const float* Wq      = (const float*)d_in[1];
    const float* Wk      = (const float*)d_in[2];
    const float* Wv      = (const float*)d_in[3];
    const float* cqw     = (const float*)d_in[4];
    const float* cqb     = (const float*)d_in[5];
    const float* ckw     = (const float*)d_in[6];
    const float* ckb     = (const float*)d_in[7];
    const float* cvw     = (const float*)d_in[8];
    const float* cvb     = (const float*)d_in[9];
    const float* Wa      = (const float*)d_in[10];
    const float* ba      = (const float*)d_in[11];
    const float* Wb      = (const float*)d_in[12];
    const float* bb      = (const float*)d_in[13];
    const float* Wg      = (const float*)d_in[14];
    const float* ln_g    = (const float*)d_in[15];
    const float* ln_b    = (const float*)d_in[16];
    const float* Wo      = (const float*)d_in[17];
    float* out = (float*)d_out;

    float *qb, *kb, *vb, *qc, *kc, *vc, *gb, *ob, *o2, *al, *be;
    cudaGetSymbolAddress((void**)&qb, g_qb);
    cudaGetSymbolAddress((void**)&kb, g_kb);
    cudaGetSymbolAddress((void**)&vb, g_vb);
    cudaGetSymbolAddress((void**)&qc, g_qc);
    cudaGetSymbolAddress((void**)&kc, g_kc);
    cudaGetSymbolAddress((void**)&vc, g_vc);
    cudaGetSymbolAddress((void**)&gb, g_gb);
    cudaGetSymbolAddress((void**)&ob, g_ob);
    cudaGetSymbolAddress((void**)&o2, g_o2);
    cudaGetSymbolAddress((void**)&al, g_alpha);
    cudaGetSymbolAddress((void**)&be, g_beta);
    __nv_bfloat16 *xh, *xl, *wh, *wl;
    cudaGetSymbolAddress((void**)&xh, g_xh);
    cudaGetSymbolAddress((void**)&xl, g_xl);
    cudaGetSymbolAddress((void**)&wh, g_wh);
    cudaGetSymbolAddress((void**)&wl, g_wl);

    const int WN = HID * HID;
    // pre-split operands to bf16 hi/lo
    split_bf16<<<S_LEN * HID / 1024, 256>>>(x, xh, xl);
    split_bf16<<<WN / 1024, 256>>>(Wq, wh + 0 * WN, wl + 0 * WN);
    split_bf16<<<WN / 1024, 256>>>(Wk, wh + 1 * WN, wl + 1 * WN);
    split_bf16<<<WN / 1024, 256>>>(Wv, wh + 2 * WN, wl + 2 * WN);
    split_bf16<<<WN / 1024, 256>>>(Wg, wh + 3 * WN, wl + 3 * WN);
    split_bf16<<<WN / 1024, 256>>>(Wo, wh + 4 * WN, wl + 4 * WN);

    dim3 gp(HID / 64, S_LEN / 128, 4);
    mm_pre<<<gp, 256>>>(xh, xl, wh, wl, qb, kb, vb, gb);

    ab_kernel<<<S_LEN, 256>>>(x, Wa, ba, Wb, bb, al, be);

    dim3 gc(S_LEN * HID / 256, 3);
    conv_silu3<<<gc, 256>>>(qb, kb, vb, cqw, cqb, ckw, ckb, cvw, cvb, qc, kc, vc);

    decay_scan   <<<NCH, 64>>>();
    chunk_mqk    <<<NCH, 256>>>();
    chunk_tinv   <<<NCH, 64>>>();
    chunk_ew     <<<NCH, 256>>>();
    chunk_scan_seq<<<128, 256>>>();
    chunk_out    <<<NCH * 4, 256>>>();

    ln_gate<<<S_LEN * NH, 128>>>(ob, gb, ln_g, ln_b, o2);

    // split o2 (reuses xh/xl) and run output GEMM
    split_bf16<<<S_LEN * HID / 1024, 256>>>(o2, xh, xl);
    dim3 go(HID / 64, S_LEN / 128, 1);
    mm_pre<<<go, 256>>>(xh, xl, wh + 4 * WN, wl + 4 * WN, out, out, out, out);
}